// round 12
// baseline (speedup 1.0000x reference)
#include <cuda_runtime.h>
#include <cuda_bf16.h>
#include <cuda.h>
#include <math.h>
#include <stdint.h>

#define D_MODEL 1024
#define NHEAD   16
#define DH      64
#define D_FF    4096
#define SEQ     2048
#define BATCH   2
#define NTOK    (SEQ * BATCH)
#define EPS     1e-5f
#define QKV_N   (3 * D_MODEL)   // 3072

// ======================= helpers ============================================
__device__ __forceinline__ uint32_t smem_to_u32(const void* p) {
    uint32_t a;
    asm("{ .reg .u64 t; cvta.to.shared.u64 t, %1; cvt.u32.u64 %0, t; }" : "=r"(a) : "l"(p));
    return a;
}
__device__ __forceinline__ void cp_async16(uint32_t dst, const void* src) {
    asm volatile("cp.async.cg.shared.global [%0], [%1], 16;" :: "r"(dst), "l"(src) : "memory");
}
#define CP_COMMIT() asm volatile("cp.async.commit_group;" ::: "memory")
#define CP_WAIT(n)  asm volatile("cp.async.wait_group %0;" :: "n"(n) : "memory")

__device__ __forceinline__ void ldm_x4(uint32_t* r, uint32_t addr) {
    asm volatile("ldmatrix.sync.aligned.m8n8.x4.shared.b16 {%0,%1,%2,%3}, [%4];"
        : "=r"(r[0]), "=r"(r[1]), "=r"(r[2]), "=r"(r[3]) : "r"(addr));
}
__device__ __forceinline__ void ldm_x4_t(uint32_t* r, uint32_t addr) {
    asm volatile("ldmatrix.sync.aligned.m8n8.x4.trans.shared.b16 {%0,%1,%2,%3}, [%4];"
        : "=r"(r[0]), "=r"(r[1]), "=r"(r[2]), "=r"(r[3]) : "r"(addr));
}
__device__ __forceinline__ void mma_bf16(float* d, const uint32_t* a, const uint32_t* b) {
    asm volatile("mma.sync.aligned.m16n8k16.row.col.f32.bf16.bf16.f32 "
        "{%0,%1,%2,%3}, {%4,%5,%6,%7}, {%8,%9}, {%0,%1,%2,%3};"
        : "+f"(d[0]), "+f"(d[1]), "+f"(d[2]), "+f"(d[3])
        : "r"(a[0]), "r"(a[1]), "r"(a[2]), "r"(a[3]), "r"(b[0]), "r"(b[1]));
}
__device__ __forceinline__ void split2(float x, __nv_bfloat16& h, __nv_bfloat16& l) {
    h = __float2bfloat16_rn(x);
    l = __float2bfloat16_rn(x - __bfloat162float(h));
}
__device__ __forceinline__ uint32_t pk(__nv_bfloat16 a, __nv_bfloat16 b) {
    __nv_bfloat162 t(a, b);
    return *reinterpret_cast<uint32_t*>(&t);
}

// ======================= scratch ============================================
__device__ float          g_XB  [NTOK * D_MODEL];
__device__ __nv_bfloat16  g_XBh [NTOK * D_MODEL];
__device__ __nv_bfloat16  g_XBl [NTOK * D_MODEL];
__device__ __nv_bfloat16  g_QKVh[NTOK * QKV_N];
__device__ __nv_bfloat16  g_QKVl[NTOK * QKV_N];
__device__ __nv_bfloat16  g_CTXh[NTOK * D_MODEL];
__device__ __nv_bfloat16  g_CTXl[NTOK * D_MODEL];
__device__ float          g_P0  [NTOK * D_MODEL];   // split-K partial 0
__device__ float          g_P1  [NTOK * D_MODEL];   // split-K partial 1
__device__ float          g_X1  [NTOK * D_MODEL];
__device__ __nv_bfloat16  g_X1h [NTOK * D_MODEL];
__device__ __nv_bfloat16  g_X1l [NTOK * D_MODEL];
__device__ __nv_bfloat16  g_Hh  [NTOK * D_FF];
__device__ __nv_bfloat16  g_Hl  [NTOK * D_FF];
__device__ __nv_bfloat16  g_Wqkvth[QKV_N * D_MODEL];
__device__ __nv_bfloat16  g_Wqkvtl[QKV_N * D_MODEL];
__device__ __nv_bfloat16  g_Woth[D_MODEL * D_MODEL];
__device__ __nv_bfloat16  g_Wotl[D_MODEL * D_MODEL];
__device__ __nv_bfloat16  g_W1th[D_FF * D_MODEL];
__device__ __nv_bfloat16  g_W1tl[D_FF * D_MODEL];
__device__ __nv_bfloat16  g_W2th[D_MODEL * D_FF];
__device__ __nv_bfloat16  g_W2tl[D_MODEL * D_FF];
__device__ float          g_bqkv[QKV_N];

// ======================= prep kernels =======================================
__global__ void transpose_in_kernel(const float* __restrict__ x, float* __restrict__ xb,
                                    __nv_bfloat16* __restrict__ xh, __nv_bfloat16* __restrict__ xl)
{
    int idx = blockIdx.x * 256 + threadIdx.x;
    int r  = idx >> 8;
    int c4 = idx & 255;
    int b_ = r / SEQ;
    int s_ = r - b_ * SEQ;
    float4 v = ((const float4*)x)[(size_t)(s_ * BATCH + b_) * 256 + c4];
    ((float4*)xb)[idx] = v;
    __nv_bfloat16 h0,l0,h1,l1,h2,l2,h3,l3;
    split2(v.x,h0,l0); split2(v.y,h1,l1); split2(v.z,h2,l2); split2(v.w,h3,l3);
    __nv_bfloat162* ph = (__nv_bfloat162*)(xh + (size_t)idx * 4);
    __nv_bfloat162* pl = (__nv_bfloat162*)(xl + (size_t)idx * 4);
    ph[0] = __nv_bfloat162(h0, h1); ph[1] = __nv_bfloat162(h2, h3);
    pl[0] = __nv_bfloat162(l0, l1); pl[1] = __nv_bfloat162(l2, l3);
}

// all six weight transposes in ONE launch; flat block id dispatch.
__global__ void transpose_split_all_kernel(
    const float* __restrict__ Wq, const float* __restrict__ Wk,
    const float* __restrict__ Wv, const float* __restrict__ Wo,
    const float* __restrict__ W1, const float* __restrict__ W2,
    __nv_bfloat16* __restrict__ Wqkvth, __nv_bfloat16* __restrict__ Wqkvtl,
    __nv_bfloat16* __restrict__ Woth,   __nv_bfloat16* __restrict__ Wotl,
    __nv_bfloat16* __restrict__ W1th,   __nv_bfloat16* __restrict__ W1tl,
    __nv_bfloat16* __restrict__ W2th,   __nv_bfloat16* __restrict__ W2tl)
{
    __shared__ float t[32][33];
    const int blk = blockIdx.x;
    const float* W; __nv_bfloat16 *Oh, *Ol;
    int K, N, bx, by;
    if (blk < 4096) {
        int m = blk >> 10;
        int j = blk & 1023;
        K = D_MODEL; N = D_MODEL;
        bx = j & 31; by = j >> 5;
        if (m == 0)      { W = Wq; Oh = Wqkvth;                                Ol = Wqkvtl; }
        else if (m == 1) { W = Wk; Oh = Wqkvth + (size_t)D_MODEL*D_MODEL;      Ol = Wqkvtl + (size_t)D_MODEL*D_MODEL; }
        else if (m == 2) { W = Wv; Oh = Wqkvth + (size_t)2*D_MODEL*D_MODEL;    Ol = Wqkvtl + (size_t)2*D_MODEL*D_MODEL; }
        else             { W = Wo; Oh = Woth;                                  Ol = Wotl; }
    } else if (blk < 8192) {
        int j = blk - 4096;
        K = D_MODEL; N = D_FF;
        bx = j & 127; by = j >> 7;
        W = W1; Oh = W1th; Ol = W1tl;
    } else {
        int j = blk - 8192;
        K = D_FF; N = D_MODEL;
        bx = j & 31; by = j >> 5;
        W = W2; Oh = W2th; Ol = W2tl;
    }
    int n0 = bx * 32, k0 = by * 32;
    int tx = threadIdx.x, ty = threadIdx.y;
#pragma unroll
    for (int i = 0; i < 4; i++)
        t[ty + 8*i][tx] = W[(size_t)(k0 + ty + 8*i) * N + n0 + tx];
    __syncthreads();
#pragma unroll
    for (int i = 0; i < 4; i++) {
        float v = t[tx][ty + 8*i];
        __nv_bfloat16 h, l; split2(v, h, l);
        size_t o = (size_t)(n0 + ty + 8*i) * K + k0 + tx;
        Oh[o] = h; Ol[o] = l;
    }
}

__global__ void concat_bias_kernel(const float* bq, const float* bk, const float* bv, float* o)
{
    int i = blockIdx.x * 256 + threadIdx.x;
    if (i < QKV_N) {
        const float* s = (i < 1024) ? bq : (i < 2048) ? bk : bv;
        o[i] = s[i & 1023];
    }
}

// ======================= HMMA bf16x3 GEMM (GK=64, 1 CTA/SM) ==================
// epi 1: +bias,GELU -> Ch,Cl ; 3: +bias -> Ch,Cl ; 4: raw fp32 -> (Cf0|Cf1 by blockIdx.z)
#define GK        64
#define ROWB      144
#define PARTB     (128 * ROWB)      // 18432
#define STAGEB    (4 * PARTB)       // 73728
#define GEMM_SMEM (2 * STAGEB)      // 147456

__global__ __launch_bounds__(256)
void gemm_hmma_kernel(const __nv_bfloat16* __restrict__ Ah, const __nv_bfloat16* __restrict__ Al,
                      const __nv_bfloat16* __restrict__ Bth, const __nv_bfloat16* __restrict__ Btl,
                      const float* __restrict__ bias,
                      float* __restrict__ Cf0, float* __restrict__ Cf1,
                      __nv_bfloat16* __restrict__ Ch, __nv_bfloat16* __restrict__ Cl,
                      int Klen, int LDK, int N, int epi)
{
    extern __shared__ char smem[];
    const uint32_t sbase = smem_to_u32(smem);

    const int tid = threadIdx.x;
    const int wid = tid >> 5;
    const int lid = tid & 31;
    const int wm = wid >> 2;
    const int wn = wid & 3;
    const int brow = blockIdx.y * 128;
    const int bcol = blockIdx.x * 128;
    const int kz = blockIdx.z;
    const int NC = Klen / GK;

    const size_t kofs = (size_t)kz * Klen;
    Ah += kofs; Al += kofs; Bth += kofs; Btl += kofs;
    float* Cf = kz ? Cf1 : Cf0;

    float acc[4][4][4];
#pragma unroll
    for (int mi = 0; mi < 4; mi++)
#pragma unroll
        for (int ni = 0; ni < 4; ni++)
#pragma unroll
            for (int e = 0; e < 4; e++) acc[mi][ni][e] = 0.f;

    // chunk = 4 parts x 128 rows x 128B (GK=64 bf16); 4096 vec16, 16/thread.
    auto load_chunk = [&](int kc, int s) {
        const int kb = kc * GK;
        const __nv_bfloat16* srcs[4] = { Ah, Al, Bth, Btl };
#pragma unroll
        for (int p = 0; p < 16; p++) {
            int i = tid + p * 256;
            int part = i >> 10;
            int j = i & 1023;
            int r = j >> 3, c = j & 7;
            int grow = ((part < 2) ? brow : bcol) + r;
            const __nv_bfloat16* src = srcs[part] + (size_t)grow * LDK + kb + c * 8;
            cp_async16(sbase + s * STAGEB + part * PARTB + r * ROWB + c * 16, src);
        }
        CP_COMMIT();
    };

    const int a_row = lid & 15;
    const int a_kof = (lid >> 4) * 8;
    const int bkey  = (lid & 7) + 8 * (lid >> 4);      // x4 B: two n-frags
    const int bkof  = ((lid >> 3) & 1) * 8;

    load_chunk(0, 0);

    for (int kc = 0; kc < NC; kc++) {
        CP_WAIT(0);
        __syncthreads();                    // buf[kc] visible; buf[kc+1] free

        const uint32_t st = sbase + (kc & 1) * STAGEB;
        const uint32_t ah_b = st;
        const uint32_t al_b = st + PARTB;
        const uint32_t bh_b = st + 2 * PARTB;
        const uint32_t bl_b = st + 3 * PARTB;

#pragma unroll
        for (int ks = 0; ks < 4; ks++) {
            const int k0 = ks * 16;
            uint32_t ahf[4][4], alf[4][4], bhf[2][4], blf[2][4];
#pragma unroll
            for (int mi = 0; mi < 4; mi++) {
                int row = wm * 64 + mi * 16 + a_row;
                uint32_t off = row * ROWB + (k0 + a_kof) * 2;
                ldm_x4(ahf[mi], ah_b + off);
                ldm_x4(alf[mi], al_b + off);
            }
#pragma unroll
            for (int nip = 0; nip < 2; nip++) {
                uint32_t off = (wn * 32 + nip * 16 + bkey) * ROWB + (k0 + bkof) * 2;
                ldm_x4(bhf[nip], bh_b + off);
                ldm_x4(blf[nip], bl_b + off);
            }
            if (ks == 0 && kc + 1 < NC) load_chunk(kc + 1, (kc + 1) & 1);

            // term-major passes (acc reuse distance 16)
#pragma unroll
            for (int mi = 0; mi < 4; mi++)
#pragma unroll
                for (int nip = 0; nip < 2; nip++) {
                    mma_bf16(acc[mi][2*nip],   ahf[mi], bhf[nip]);
                    mma_bf16(acc[mi][2*nip+1], ahf[mi], bhf[nip] + 2);
                }
#pragma unroll
            for (int mi = 0; mi < 4; mi++)
#pragma unroll
                for (int nip = 0; nip < 2; nip++) {
                    mma_bf16(acc[mi][2*nip],   ahf[mi], blf[nip]);
                    mma_bf16(acc[mi][2*nip+1], ahf[mi], blf[nip] + 2);
                }
#pragma unroll
            for (int mi = 0; mi < 4; mi++)
#pragma unroll
                for (int nip = 0; nip < 2; nip++) {
                    mma_bf16(acc[mi][2*nip],   alf[mi], bhf[nip]);
                    mma_bf16(acc[mi][2*nip+1], alf[mi], bhf[nip] + 2);
                }
        }
    }

    const int r_in = lid >> 2;
    const int c_in = (lid & 3) * 2;
#pragma unroll
    for (int mi = 0; mi < 4; mi++) {
#pragma unroll
        for (int ni = 0; ni < 4; ni++) {
            int row0 = brow + wm * 64 + mi * 16 + r_in;
            int col  = bcol + wn * 32 + ni * 8 + c_in;
            size_t i0 = (size_t)row0 * N + col;
            size_t i1 = (size_t)(row0 + 8) * N + col;
            if (epi == 4) {
                *(float2*)&Cf[i0] = make_float2(acc[mi][ni][0], acc[mi][ni][1]);
                *(float2*)&Cf[i1] = make_float2(acc[mi][ni][2], acc[mi][ni][3]);
            } else {
                float2 bv = *(const float2*)&bias[col];
                float v[4];
                v[0] = acc[mi][ni][0] + bv.x;
                v[1] = acc[mi][ni][1] + bv.y;
                v[2] = acc[mi][ni][2] + bv.x;
                v[3] = acc[mi][ni][3] + bv.y;
                if (epi == 1) {
#pragma unroll
                    for (int e = 0; e < 4; e++)
                        v[e] = 0.5f * v[e] * (1.f + erff(v[e] * 0.70710678118654752f));
                }
                __nv_bfloat16 h0,l0,h1,l1;
                split2(v[0], h0, l0); split2(v[1], h1, l1);
                *(__nv_bfloat162*)&Ch[i0] = __nv_bfloat162(h0, h1);
                *(__nv_bfloat162*)&Cl[i0] = __nv_bfloat162(l0, l1);
                split2(v[2], h0, l0); split2(v[3], h1, l1);
                *(__nv_bfloat162*)&Ch[i1] = __nv_bfloat162(h0, h1);
                *(__nv_bfloat162*)&Cl[i1] = __nv_bfloat162(l0, l1);
            }
        }
    }
}

// ======================= HMMA flash attention ================================
#define AP_B    144
#define KV_PART (64 * AP_B)                 // 9216
#define ATT_SMEM (8 * KV_PART)              // 73728

__global__ __launch_bounds__(256)
void attention_hmma_kernel(const __nv_bfloat16* __restrict__ QKVh,
                           const __nv_bfloat16* __restrict__ QKVl,
                           __nv_bfloat16* __restrict__ Oh, __nv_bfloat16* __restrict__ Ol)
{
    extern __shared__ char smem[];
    const uint32_t sbase = smem_to_u32(smem);
    const int tid = threadIdx.x, wid = tid >> 5, lid = tid & 31;
    const int qt = blockIdx.x, bh = blockIdx.y;
    const int b_ = bh >> 4, h_ = bh & 15;
    const int qrow0 = b_ * SEQ + qt * 128;
    const int krow0 = b_ * SEQ;
    const size_t LDQ = QKV_N;

    {
        const __nv_bfloat16* srcs[2] = { QKVh, QKVl };
#pragma unroll
        for (int t = 0; t < 8; t++) {
            int i = tid + t * 256;
            int part = i >> 10, j = i & 1023, r = j >> 3, c = j & 7;
            cp_async16(sbase + part * (2 * KV_PART) + r * AP_B + c * 16,
                       srcs[part] + (size_t)(qrow0 + r) * LDQ + h_ * 64 + c * 8);
        }
        CP_COMMIT();
    }
    CP_WAIT(0);
    __syncthreads();

    uint32_t aQh[4][4], aQl[4][4];
    {
        const int arow = lid & 15, akof = (lid >> 4) * 8;
#pragma unroll
        for (int ks = 0; ks < 4; ks++) {
            uint32_t off = (wid * 16 + arow) * AP_B + (ks * 16 + akof) * 2;
            ldm_x4(aQh[ks], sbase + off);
            ldm_x4(aQl[ks], sbase + 2 * KV_PART + off);
        }
    }
    __syncthreads();

    auto load_kv = [&](int kt, int s) {
        const __nv_bfloat16* srcs[4] = { QKVh, QKVl, QKVh, QKVl };
        const int coff[4] = { 1024, 1024, 2048, 2048 };
#pragma unroll
        for (int t = 0; t < 8; t++) {
            int i = tid + t * 256;
            int part = i >> 9, j = i & 511, r = j >> 3, c = j & 7;
            cp_async16(sbase + s * (4 * KV_PART) + part * KV_PART + r * AP_B + c * 16,
                       srcs[part] + (size_t)(krow0 + kt * 64 + r) * LDQ + coff[part] + h_ * 64 + c * 8);
        }
        CP_COMMIT();
    };
    load_kv(0, 0);

    float m0 = -INFINITY, m1 = -INFINITY, l0 = 0.f, l1 = 0.f;
    float oA[8][4];
#pragma unroll
    for (int ni = 0; ni < 8; ni++)
#pragma unroll
        for (int e = 0; e < 4; e++) oA[ni][e] = 0.f;

    const int bkey = (lid & 7) + 8 * (lid >> 4);
    const int bkof = ((lid >> 3) & 1) * 8;
    const int vkey = (lid & 7) + 8 * ((lid >> 3) & 1);
    const int vdh  = (lid >> 4) * 8;

    for (int kt = 0; kt < 32; kt++) {
        CP_WAIT(0);
        __syncthreads();
        if (kt < 31) load_kv(kt + 1, (kt + 1) & 1);
        const uint32_t kb = sbase + (kt & 1) * (4 * KV_PART);

        float sc[8][4];
#pragma unroll
        for (int ni = 0; ni < 8; ni++)
#pragma unroll
            for (int e = 0; e < 4; e++) sc[ni][e] = 0.f;

#pragma unroll
        for (int ks = 0; ks < 4; ks++) {
            uint32_t bh4[4][4], bl4[4][4];
#pragma unroll
            for (int nip = 0; nip < 4; nip++) {
                uint32_t off = (nip * 16 + bkey) * AP_B + (ks * 16 + bkof) * 2;
                ldm_x4(bh4[nip], kb + off);
                ldm_x4(bl4[nip], kb + KV_PART + off);
            }
#pragma unroll
            for (int nip = 0; nip < 4; nip++) {
                mma_bf16(sc[2*nip],   aQh[ks], bh4[nip]);
                mma_bf16(sc[2*nip+1], aQh[ks], bh4[nip] + 2);
            }
#pragma unroll
            for (int nip = 0; nip < 4; nip++) {
                mma_bf16(sc[2*nip],   aQh[ks], bl4[nip]);
                mma_bf16(sc[2*nip+1], aQh[ks], bl4[nip] + 2);
            }
#pragma unroll
            for (int nip = 0; nip < 4; nip++) {
                mma_bf16(sc[2*nip],   aQl[ks], bh4[nip]);
                mma_bf16(sc[2*nip+1], aQl[ks], bh4[nip] + 2);
            }
        }

        float mx0 = -INFINITY, mx1 = -INFINITY;
#pragma unroll
        for (int ni = 0; ni < 8; ni++) {
#pragma unroll
            for (int e = 0; e < 4; e++) sc[ni][e] *= 0.125f;
            mx0 = fmaxf(mx0, fmaxf(sc[ni][0], sc[ni][1]));
            mx1 = fmaxf(mx1, fmaxf(sc[ni][2], sc[ni][3]));
        }
        mx0 = fmaxf(mx0, __shfl_xor_sync(0xffffffffu, mx0, 1));
        mx0 = fmaxf(mx0, __shfl_xor_sync(0xffffffffu, mx0, 2));
        mx1 = fmaxf(mx1, __shfl_xor_sync(0xffffffffu, mx1, 1));
        mx1 = fmaxf(mx1, __shfl_xor_sync(0xffffffffu, mx1, 2));
        float mn0 = fmaxf(m0, mx0), mn1 = fmaxf(m1, mx1);
        float f0 = __expf(m0 - mn0), f1 = __expf(m1 - mn1);
        float r0 = 0.f, r1 = 0.f;
#pragma unroll
        for (int ni = 0; ni < 8; ni++) {
            sc[ni][0] = __expf(sc[ni][0] - mn0);
            sc[ni][1] = __expf(sc[ni][1] - mn0);
            sc[ni][2] = __expf(sc[ni][2] - mn1);
            sc[ni][3] = __expf(sc[ni][3] - mn1);
            r0 += sc[ni][0] + sc[ni][1];
            r1 += sc[ni][2] + sc[ni][3];
        }
        r0 += __shfl_xor_sync(0xffffffffu, r0, 1);
        r0 += __shfl_xor_sync(0xffffffffu, r0, 2);
        r1 += __shfl_xor_sync(0xffffffffu, r1, 1);
        r1 += __shfl_xor_sync(0xffffffffu, r1, 2);
        l0 = l0 * f0 + r0;  l1 = l1 * f1 + r1;
        m0 = mn0;           m1 = mn1;
#pragma unroll
        for (int ni = 0; ni < 8; ni++) {
            oA[ni][0] *= f0; oA[ni][1] *= f0;
            oA[ni][2] *= f1; oA[ni][3] *= f1;
        }

#pragma unroll
        for (int ks = 0; ks < 4; ks++) {
            uint32_t ah[4], al[4];
            {
                __nv_bfloat16 h0,l0b,h1,l1b;
                split2(sc[2*ks][0],h0,l0b);   split2(sc[2*ks][1],h1,l1b);   ah[0]=pk(h0,h1); al[0]=pk(l0b,l1b);
                split2(sc[2*ks][2],h0,l0b);   split2(sc[2*ks][3],h1,l1b);   ah[1]=pk(h0,h1); al[1]=pk(l0b,l1b);
                split2(sc[2*ks+1][0],h0,l0b); split2(sc[2*ks+1][1],h1,l1b); ah[2]=pk(h0,h1); al[2]=pk(l0b,l1b);
                split2(sc[2*ks+1][2],h0,l0b); split2(sc[2*ks+1][3],h1,l1b); ah[3]=pk(h0,h1); al[3]=pk(l0b,l1b);
            }
            uint32_t vh4[4][4], vl4[4][4];
#pragma unroll
            for (int nip = 0; nip < 4; nip++) {
                uint32_t off = (ks * 16 + vkey) * AP_B + (nip * 16 + vdh) * 2;
                ldm_x4_t(vh4[nip], kb + 2 * KV_PART + off);
                ldm_x4_t(vl4[nip], kb + 3 * KV_PART + off);
            }
#pragma unroll
            for (int nip = 0; nip < 4; nip++) {
                mma_bf16(oA[2*nip],   ah, vh4[nip]);
                mma_bf16(oA[2*nip+1], ah, vh4[nip] + 2);
            }
#pragma unroll
            for (int nip = 0; nip < 4; nip++) {
                mma_bf16(oA[2*nip],   ah, vl4[nip]);
                mma_bf16(oA[2*nip+1], ah, vl4[nip] + 2);
            }
#pragma unroll
            for (int nip = 0; nip < 4; nip++) {
                mma_bf16(oA[2*nip],   al, vh4[nip]);
                mma_bf16(oA[2*nip+1], al, vh4[nip] + 2);
            }
        }
    }

    const float inv0 = 1.f / l0, inv1 = 1.f / l1;
    const int row0 = qrow0 + wid * 16 + (lid >> 2);
    const int colb = h_ * 64 + (lid & 3) * 2;
#pragma unroll
    for (int ni = 0; ni < 8; ni++) {
        int col = colb + ni * 8;
        __nv_bfloat16 h0,lo0,h1,lo1;
        split2(oA[ni][0] * inv0, h0, lo0);
        split2(oA[ni][1] * inv0, h1, lo1);
        size_t i0 = (size_t)row0 * D_MODEL + col;
        *(__nv_bfloat162*)&Oh[i0] = __nv_bfloat162(h0, h1);
        *(__nv_bfloat162*)&Ol[i0] = __nv_bfloat162(lo0, lo1);
        split2(oA[ni][2] * inv1, h0, lo0);
        split2(oA[ni][3] * inv1, h1, lo1);
        size_t i1 = (size_t)(row0 + 8) * D_MODEL + col;
        *(__nv_bfloat162*)&Oh[i1] = __nv_bfloat162(h0, h1);
        *(__nv_bfloat162*)&Ol[i1] = __nv_bfloat162(lo0, lo1);
    }
}

// ======================= fused split-K reduce + layernorm ====================
__global__ void layernorm_sum_kernel(const float* __restrict__ P0, const float* __restrict__ P1,
                                     const float* __restrict__ bias, const float* __restrict__ Res,
                                     const float* __restrict__ g, const float* __restrict__ be,
                                     float* __restrict__ out,
                                     __nv_bfloat16* __restrict__ oh, __nv_bfloat16* __restrict__ ol,
                                     int transpose_out)
{
    __shared__ float rs[8], rq[8];
    const int row = blockIdx.x;
    const int tid = threadIdx.x;

    float4 a = ((const float4*)(P0 + (size_t)row * D_MODEL))[tid];
    float4 b = ((const float4*)(P1 + (size_t)row * D_MODEL))[tid];
    float4 r = ((const float4*)(Res + (size_t)row * D_MODEL))[tid];
    float4 bb = ((const float4*)bias)[tid];
    float4 v;
    v.x = a.x + b.x + bb.x + r.x;
    v.y = a.y + b.y + bb.y + r.y;
    v.z = a.z + b.z + bb.z + r.z;
    v.w = a.w + b.w + bb.w + r.w;

    float s = v.x + v.y + v.z + v.w;
    float q = v.x*v.x + v.y*v.y + v.z*v.z + v.w*v.w;
#pragma unroll
    for (int o = 16; o >= 1; o >>= 1) {
        s += __shfl_xor_sync(0xffffffffu, s, o);
        q += __shfl_xor_sync(0xffffffffu, q, o);
    }
    if ((tid & 31) == 0) { rs[tid >> 5] = s; rq[tid >> 5] = q; }
    __syncthreads();
    s = 0.f; q = 0.f;
#pragma unroll
    for (int i = 0; i < 8; i++) { s += rs[i]; q += rq[i]; }

    float mean = s * (1.f / D_MODEL);
    float var  = q * (1.f / D_MODEL) - mean * mean;
    float rstd = rsqrtf(var + EPS);

    float4 g4 = ((const float4*)g)[tid];
    float4 b4 = ((const float4*)be)[tid];
    float4 o4;
    o4.x = (v.x - mean) * rstd * g4.x + b4.x;
    o4.y = (v.y - mean) * rstd * g4.y + b4.y;
    o4.z = (v.z - mean) * rstd * g4.z + b4.z;
    o4.w = (v.w - mean) * rstd * g4.w + b4.w;

    size_t orow = row;
    if (transpose_out) {
        int b_ = row >> 11;
        int s_ = row & 2047;
        orow = (size_t)s_ * BATCH + b_;
    }
    ((float4*)(out + orow * D_MODEL))[tid] = o4;

    if (oh) {
        __nv_bfloat16 h0,l0,h1,l1,h2,l2,h3,l3;
        split2(o4.x,h0,l0); split2(o4.y,h1,l1); split2(o4.z,h2,l2); split2(o4.w,h3,l3);
        size_t o = (size_t)row * D_MODEL + tid * 4;
        *(__nv_bfloat162*)(oh + o)     = __nv_bfloat162(h0, h1);
        *(__nv_bfloat162*)(oh + o + 2) = __nv_bfloat162(h2, h3);
        *(__nv_bfloat162*)(ol + o)     = __nv_bfloat162(l0, l1);
        *(__nv_bfloat162*)(ol + o + 2) = __nv_bfloat162(l2, l3);
    }
}

// ======================= launch =============================================
extern "C" void kernel_launch(void* const* d_in, const int* in_sizes, int n_in,
                              void* d_out, int out_size)
{
    const float* x   = (const float*)d_in[0];
    const float* Wq  = (const float*)d_in[1];
    const float* bq  = (const float*)d_in[2];
    const float* Wk  = (const float*)d_in[3];
    const float* bk  = (const float*)d_in[4];
    const float* Wv  = (const float*)d_in[5];
    const float* bv  = (const float*)d_in[6];
    const float* Wo  = (const float*)d_in[7];
    const float* bo  = (const float*)d_in[8];
    const float* W1  = (const float*)d_in[9];
    const float* b1  = (const float*)d_in[10];
    const float* W2  = (const float*)d_in[11];
    const float* b2  = (const float*)d_in[12];
    const float* g1  = (const float*)d_in[13];
    const float* be1 = (const float*)d_in[14];
    const float* g2  = (const float*)d_in[15];
    const float* be2 = (const float*)d_in[16];
    float* out = (float*)d_out;

    float *XB, *P0, *P1, *X1, *bqkv;
    __nv_bfloat16 *XBh, *XBl, *QKVh, *QKVl, *CTXh, *CTXl, *X1h, *X1l, *Hh, *Hl;
    __nv_bfloat16 *Wqkvth, *Wqkvtl, *Woth, *Wotl, *W1th, *W1tl, *W2th, *W2tl;
    cudaGetSymbolAddress((void**)&XB,   g_XB);
    cudaGetSymbolAddress((void**)&XBh,  g_XBh);
    cudaGetSymbolAddress((void**)&XBl,  g_XBl);
    cudaGetSymbolAddress((void**)&QKVh, g_QKVh);
    cudaGetSymbolAddress((void**)&QKVl, g_QKVl);
    cudaGetSymbolAddress((void**)&CTXh, g_CTXh);
    cudaGetSymbolAddress((void**)&CTXl, g_CTXl);
    cudaGetSymbolAddress((void**)&P0,   g_P0);
    cudaGetSymbolAddress((void**)&P1,   g_P1);
    cudaGetSymbolAddress((void**)&X1,   g_X1);
    cudaGetSymbolAddress((void**)&X1h,  g_X1h);
    cudaGetSymbolAddress((void**)&X1l,  g_X1l);
    cudaGetSymbolAddress((void**)&Hh,   g_Hh);
    cudaGetSymbolAddress((void**)&Hl,   g_Hl);
    cudaGetSymbolAddress((void**)&Wqkvth, g_Wqkvth);
    cudaGetSymbolAddress((void**)&Wqkvtl, g_Wqkvtl);
    cudaGetSymbolAddress((void**)&Woth, g_Woth);
    cudaGetSymbolAddress((void**)&Wotl, g_Wotl);
    cudaGetSymbolAddress((void**)&W1th, g_W1th);
    cudaGetSymbolAddress((void**)&W1tl, g_W1tl);
    cudaGetSymbolAddress((void**)&W2th, g_W2th);
    cudaGetSymbolAddress((void**)&W2tl, g_W2tl);
    cudaGetSymbolAddress((void**)&bqkv, g_bqkv);

    cudaFuncSetAttribute(gemm_hmma_kernel, cudaFuncAttributeMaxDynamicSharedMemorySize, GEMM_SMEM);
    cudaFuncSetAttribute(attention_hmma_kernel, cudaFuncAttributeMaxDynamicSharedMemorySize, ATT_SMEM);

    // prep
    transpose_in_kernel<<<4096, 256>>>(x, XB, XBh, XBl);
    transpose_split_all_kernel<<<12288, dim3(32, 8)>>>(
        Wq, Wk, Wv, Wo, W1, W2,
        Wqkvth, Wqkvtl, Woth, Wotl, W1th, W1tl, W2th, W2tl);
    concat_bias_kernel<<<(QKV_N + 255)/256, 256>>>(bq, bk, bv, bqkv);

    // fused QKV -> bf16 hi/lo (epi 3)
    gemm_hmma_kernel<<<dim3(QKV_N/128, NTOK/128, 1), 256, GEMM_SMEM>>>(
        XBh, XBl, Wqkvth, Wqkvtl, bqkv, nullptr, nullptr, QKVh, QKVl,
        D_MODEL, D_MODEL, QKV_N, 3);

    // HMMA flash attention -> CTX hi/lo
    attention_hmma_kernel<<<dim3(SEQ/128, BATCH*NHEAD), 256, ATT_SMEM>>>(QKVh, QKVl, CTXh, CTXl);

    // O-proj split-K=2 (raw partials) ; fused reduce+bias+res+LN1 -> X1 (+hi/lo)
    gemm_hmma_kernel<<<dim3(D_MODEL/128, NTOK/128, 2), 256, GEMM_SMEM>>>(
        CTXh, CTXl, Woth, Wotl, nullptr, P0, P1, nullptr, nullptr,
        D_MODEL/2, D_MODEL, D_MODEL, 4);
    layernorm_sum_kernel<<<NTOK, 256>>>(P0, P1, bo, XB, g1, be1, X1, X1h, X1l, 0);

    // FFN1 (+GELU) -> H hi/lo (epi 1)
    gemm_hmma_kernel<<<dim3(D_FF/128, NTOK/128, 1), 256, GEMM_SMEM>>>(
        X1h, X1l, W1th, W1tl, b1, nullptr, nullptr, Hh, Hl,
        D_MODEL, D_MODEL, D_FF, 1);

    // FFN2 split-K=2 (raw partials) ; fused reduce+bias+res+LN2 -> out (transposed)
    gemm_hmma_kernel<<<dim3(D_MODEL/128, NTOK/128, 2), 256, GEMM_SMEM>>>(
        Hh, Hl, W2th, W2tl, nullptr, P0, P1, nullptr, nullptr,
        D_FF/2, D_FF, D_MODEL, 4);
    layernorm_sum_kernel<<<NTOK, 256>>>(P0, P1, b2, X1, g2, be2, out, nullptr, nullptr, 1);
}

// round 13
// speedup vs baseline: 1.0670x; 1.0670x over previous
#include <cuda_runtime.h>
#include <cuda_bf16.h>
#include <cuda.h>
#include <math.h>
#include <stdint.h>

#define D_MODEL 1024
#define NHEAD   16
#define DH      64
#define D_FF    4096
#define SEQ     2048
#define BATCH   2
#define NTOK    (SEQ * BATCH)
#define EPS     1e-5f
#define QKV_N   (3 * D_MODEL)   // 3072

// ======================= helpers ============================================
__device__ __forceinline__ uint32_t smem_to_u32(const void* p) {
    uint32_t a;
    asm("{ .reg .u64 t; cvta.to.shared.u64 t, %1; cvt.u32.u64 %0, t; }" : "=r"(a) : "l"(p));
    return a;
}
__device__ __forceinline__ void cp_async16(uint32_t dst, const void* src) {
    asm volatile("cp.async.cg.shared.global [%0], [%1], 16;" :: "r"(dst), "l"(src) : "memory");
}
#define CP_COMMIT() asm volatile("cp.async.commit_group;" ::: "memory")
#define CP_WAIT(n)  asm volatile("cp.async.wait_group %0;" :: "n"(n) : "memory")

__device__ __forceinline__ void ldm_x4(uint32_t* r, uint32_t addr) {
    asm volatile("ldmatrix.sync.aligned.m8n8.x4.shared.b16 {%0,%1,%2,%3}, [%4];"
        : "=r"(r[0]), "=r"(r[1]), "=r"(r[2]), "=r"(r[3]) : "r"(addr));
}
__device__ __forceinline__ void ldm_x4_t(uint32_t* r, uint32_t addr) {
    asm volatile("ldmatrix.sync.aligned.m8n8.x4.trans.shared.b16 {%0,%1,%2,%3}, [%4];"
        : "=r"(r[0]), "=r"(r[1]), "=r"(r[2]), "=r"(r[3]) : "r"(addr));
}
__device__ __forceinline__ void mma_bf16(float* d, const uint32_t* a, const uint32_t* b) {
    asm volatile("mma.sync.aligned.m16n8k16.row.col.f32.bf16.bf16.f32 "
        "{%0,%1,%2,%3}, {%4,%5,%6,%7}, {%8,%9}, {%0,%1,%2,%3};"
        : "+f"(d[0]), "+f"(d[1]), "+f"(d[2]), "+f"(d[3])
        : "r"(a[0]), "r"(a[1]), "r"(a[2]), "r"(a[3]), "r"(b[0]), "r"(b[1]));
}
__device__ __forceinline__ void split2(float x, __nv_bfloat16& h, __nv_bfloat16& l) {
    h = __float2bfloat16_rn(x);
    l = __float2bfloat16_rn(x - __bfloat162float(h));
}
__device__ __forceinline__ uint32_t pk(__nv_bfloat16 a, __nv_bfloat16 b) {
    __nv_bfloat162 t(a, b);
    return *reinterpret_cast<uint32_t*>(&t);
}

// ======================= scratch ============================================
__device__ float          g_XB  [NTOK * D_MODEL];
__device__ __nv_bfloat16  g_XBh [NTOK * D_MODEL];
__device__ __nv_bfloat16  g_XBl [NTOK * D_MODEL];
__device__ __nv_bfloat16  g_QKVh[NTOK * QKV_N];
__device__ __nv_bfloat16  g_QKVl[NTOK * QKV_N];
__device__ __nv_bfloat16  g_CTXh[NTOK * D_MODEL];
__device__ __nv_bfloat16  g_CTXl[NTOK * D_MODEL];
__device__ float          g_P0  [NTOK * D_MODEL];
__device__ float          g_P1  [NTOK * D_MODEL];
__device__ float          g_X1  [NTOK * D_MODEL];
__device__ __nv_bfloat16  g_X1h [NTOK * D_MODEL];
__device__ __nv_bfloat16  g_X1l [NTOK * D_MODEL];
__device__ __nv_bfloat16  g_Hh  [NTOK * D_FF];
__device__ __nv_bfloat16  g_Hl  [NTOK * D_FF];
__device__ __nv_bfloat16  g_Wqkvth[QKV_N * D_MODEL];
__device__ __nv_bfloat16  g_Wqkvtl[QKV_N * D_MODEL];
__device__ __nv_bfloat16  g_Woth[D_MODEL * D_MODEL];
__device__ __nv_bfloat16  g_Wotl[D_MODEL * D_MODEL];
__device__ __nv_bfloat16  g_W1th[D_FF * D_MODEL];
__device__ __nv_bfloat16  g_W1tl[D_FF * D_MODEL];
__device__ __nv_bfloat16  g_W2th[D_MODEL * D_FF];
__device__ __nv_bfloat16  g_W2tl[D_MODEL * D_FF];
__device__ float          g_bqkv[QKV_N];

// ======================= fused prep kernel ===================================
// one launch does everything:
//  blocks [0, 12288)        : weight transposes (Wq|Wk|Wv|Wo|W1|W2) 32x32 tiles
//  blocks [12288, 16384)    : x [S,B,D] -> XB fp32 + bf16 hi/lo
//  blocks [16384, 16396)    : qkv bias concat
__global__ void prep_all_kernel(
    const float* __restrict__ x,
    const float* __restrict__ Wq, const float* __restrict__ Wk,
    const float* __restrict__ Wv, const float* __restrict__ Wo,
    const float* __restrict__ W1, const float* __restrict__ W2,
    const float* __restrict__ bq, const float* __restrict__ bk, const float* __restrict__ bv,
    float* __restrict__ xb, __nv_bfloat16* __restrict__ xh, __nv_bfloat16* __restrict__ xl,
    __nv_bfloat16* __restrict__ Wqkvth, __nv_bfloat16* __restrict__ Wqkvtl,
    __nv_bfloat16* __restrict__ Woth,   __nv_bfloat16* __restrict__ Wotl,
    __nv_bfloat16* __restrict__ W1th,   __nv_bfloat16* __restrict__ W1tl,
    __nv_bfloat16* __restrict__ W2th,   __nv_bfloat16* __restrict__ W2tl,
    float* __restrict__ bqkv)
{
    __shared__ float t[32][33];
    const int blk = blockIdx.x;
    const int tid = threadIdx.x;            // 256 threads flat

    if (blk >= 16384) {                      // ---- bias concat ----
        int i = (blk - 16384) * 256 + tid;
        if (i < QKV_N) {
            const float* s = (i < 1024) ? bq : (i < 2048) ? bk : bv;
            bqkv[i] = s[i & 1023];
        }
        return;
    }
    if (blk >= 12288) {                      // ---- input transpose + split ----
        int idx = (blk - 12288) * 256 + tid;
        int r  = idx >> 8;
        int c4 = idx & 255;
        int b_ = r / SEQ;
        int s_ = r - b_ * SEQ;
        float4 v = ((const float4*)x)[(size_t)(s_ * BATCH + b_) * 256 + c4];
        ((float4*)xb)[idx] = v;
        __nv_bfloat16 h0,l0,h1,l1,h2,l2,h3,l3;
        split2(v.x,h0,l0); split2(v.y,h1,l1); split2(v.z,h2,l2); split2(v.w,h3,l3);
        __nv_bfloat162* ph = (__nv_bfloat162*)(xh + (size_t)idx * 4);
        __nv_bfloat162* pl = (__nv_bfloat162*)(xl + (size_t)idx * 4);
        ph[0] = __nv_bfloat162(h0, h1); ph[1] = __nv_bfloat162(h2, h3);
        pl[0] = __nv_bfloat162(l0, l1); pl[1] = __nv_bfloat162(l2, l3);
        return;
    }

    // ---- weight transpose + split ----
    const float* W; __nv_bfloat16 *Oh, *Ol;
    int K, N, bx, by;
    if (blk < 4096) {
        int m = blk >> 10;
        int j = blk & 1023;
        K = D_MODEL; N = D_MODEL;
        bx = j & 31; by = j >> 5;
        if (m == 0)      { W = Wq; Oh = Wqkvth;                                Ol = Wqkvtl; }
        else if (m == 1) { W = Wk; Oh = Wqkvth + (size_t)D_MODEL*D_MODEL;      Ol = Wqkvtl + (size_t)D_MODEL*D_MODEL; }
        else if (m == 2) { W = Wv; Oh = Wqkvth + (size_t)2*D_MODEL*D_MODEL;    Ol = Wqkvtl + (size_t)2*D_MODEL*D_MODEL; }
        else             { W = Wo; Oh = Woth;                                  Ol = Wotl; }
    } else if (blk < 8192) {
        int j = blk - 4096;
        K = D_MODEL; N = D_FF;
        bx = j & 127; by = j >> 7;
        W = W1; Oh = W1th; Ol = W1tl;
    } else {
        int j = blk - 8192;
        K = D_FF; N = D_MODEL;
        bx = j & 31; by = j >> 5;
        W = W2; Oh = W2th; Ol = W2tl;
    }
    int n0 = bx * 32, k0 = by * 32;
    int tx = tid & 31, ty = tid >> 5;        // (32, 8)
#pragma unroll
    for (int i = 0; i < 4; i++)
        t[ty + 8*i][tx] = W[(size_t)(k0 + ty + 8*i) * N + n0 + tx];
    __syncthreads();
#pragma unroll
    for (int i = 0; i < 4; i++) {
        float v = t[tx][ty + 8*i];
        __nv_bfloat16 h, l; split2(v, h, l);
        size_t o = (size_t)(n0 + ty + 8*i) * K + k0 + tx;
        Oh[o] = h; Ol[o] = l;
    }
}

// ======================= HMMA bf16x3 GEMM (R11 geometry) =====================
// epi 1: +bias,GELU -> Ch,Cl ; 3: +bias -> Ch,Cl ; 4: raw fp32 -> (Cf0|Cf1 by blockIdx.z)
#define GK        32
#define ROWB      80
#define PARTB     (128 * ROWB)
#define STAGEB    (4 * PARTB)
#define GEMM_SMEM (2 * STAGEB)

__global__ __launch_bounds__(256, 2)
void gemm_hmma_kernel(const __nv_bfloat16* __restrict__ Ah, const __nv_bfloat16* __restrict__ Al,
                      const __nv_bfloat16* __restrict__ Bth, const __nv_bfloat16* __restrict__ Btl,
                      const float* __restrict__ bias,
                      float* __restrict__ Cf0, float* __restrict__ Cf1,
                      __nv_bfloat16* __restrict__ Ch, __nv_bfloat16* __restrict__ Cl,
                      int Klen, int LDK, int N, int epi)
{
    extern __shared__ char smem[];
    const uint32_t sbase = smem_to_u32(smem);

    const int tid = threadIdx.x;
    const int wid = tid >> 5;
    const int lid = tid & 31;
    const int wm = wid >> 2;
    const int wn = wid & 3;
    const int brow = blockIdx.y * 128;
    const int bcol = blockIdx.x * 128;
    const int kz = blockIdx.z;
    const int NC = Klen / GK;

    const size_t kofs = (size_t)kz * Klen;
    Ah += kofs; Al += kofs; Bth += kofs; Btl += kofs;
    float* Cf = kz ? Cf1 : Cf0;

    float acc[4][4][4];
#pragma unroll
    for (int mi = 0; mi < 4; mi++)
#pragma unroll
        for (int ni = 0; ni < 4; ni++)
#pragma unroll
            for (int e = 0; e < 4; e++) acc[mi][ni][e] = 0.f;

    auto load_chunk = [&](int kc, int s) {
        const int kb = kc * GK;
        const __nv_bfloat16* srcs[4] = { Ah, Al, Bth, Btl };
#pragma unroll
        for (int p = 0; p < 8; p++) {
            int i = tid + p * 256;
            int part = i >> 9;
            int j = i & 511;
            int r = j >> 2, c = j & 3;
            int grow = ((part < 2) ? brow : bcol) + r;
            const __nv_bfloat16* src = srcs[part] + (size_t)grow * LDK + kb + c * 8;
            cp_async16(sbase + s * STAGEB + part * PARTB + r * ROWB + c * 16, src);
        }
        CP_COMMIT();
    };

    const int a_row = lid & 15;
    const int a_kof = (lid >> 4) * 8;
    const int bkey  = (lid & 7) + 8 * (lid >> 4);
    const int bkof  = ((lid >> 3) & 1) * 8;

    load_chunk(0, 0);

    for (int kc = 0; kc < NC; kc++) {
        CP_WAIT(0);
        __syncthreads();

        const uint32_t st = sbase + (kc & 1) * STAGEB;
        const uint32_t ah_b = st;
        const uint32_t al_b = st + PARTB;
        const uint32_t bh_b = st + 2 * PARTB;
        const uint32_t bl_b = st + 3 * PARTB;

        // ---- ks = 0: LDSM first, then next-chunk cp.async ----
        uint32_t ahf[4][4], alf[4][4], bhf[2][4], blf[2][4];
#pragma unroll
        for (int mi = 0; mi < 4; mi++) {
            int row = wm * 64 + mi * 16 + a_row;
            uint32_t off = row * ROWB + a_kof * 2;
            ldm_x4(ahf[mi], ah_b + off);
            ldm_x4(alf[mi], al_b + off);
        }
#pragma unroll
        for (int nip = 0; nip < 2; nip++) {
            uint32_t off = (wn * 32 + nip * 16 + bkey) * ROWB + bkof * 2;
            ldm_x4(bhf[nip], bh_b + off);
            ldm_x4(blf[nip], bl_b + off);
        }
        if (kc + 1 < NC) load_chunk(kc + 1, (kc + 1) & 1);

#pragma unroll
        for (int mi = 0; mi < 4; mi++)
#pragma unroll
            for (int nip = 0; nip < 2; nip++) {
                mma_bf16(acc[mi][2*nip],   ahf[mi], bhf[nip]);
                mma_bf16(acc[mi][2*nip+1], ahf[mi], bhf[nip] + 2);
                mma_bf16(acc[mi][2*nip],   ahf[mi], blf[nip]);
                mma_bf16(acc[mi][2*nip+1], ahf[mi], blf[nip] + 2);
                mma_bf16(acc[mi][2*nip],   alf[mi], bhf[nip]);
                mma_bf16(acc[mi][2*nip+1], alf[mi], bhf[nip] + 2);
            }

        // ---- ks = 1 ----
#pragma unroll
        for (int mi = 0; mi < 4; mi++) {
            int row = wm * 64 + mi * 16 + a_row;
            uint32_t off = row * ROWB + (16 + a_kof) * 2;
            ldm_x4(ahf[mi], ah_b + off);
            ldm_x4(alf[mi], al_b + off);
        }
#pragma unroll
        for (int nip = 0; nip < 2; nip++) {
            uint32_t off = (wn * 32 + nip * 16 + bkey) * ROWB + (16 + bkof) * 2;
            ldm_x4(bhf[nip], bh_b + off);
            ldm_x4(blf[nip], bl_b + off);
        }
#pragma unroll
        for (int mi = 0; mi < 4; mi++)
#pragma unroll
            for (int nip = 0; nip < 2; nip++) {
                mma_bf16(acc[mi][2*nip],   ahf[mi], bhf[nip]);
                mma_bf16(acc[mi][2*nip+1], ahf[mi], bhf[nip] + 2);
                mma_bf16(acc[mi][2*nip],   ahf[mi], blf[nip]);
                mma_bf16(acc[mi][2*nip+1], ahf[mi], blf[nip] + 2);
                mma_bf16(acc[mi][2*nip],   alf[mi], bhf[nip]);
                mma_bf16(acc[mi][2*nip+1], alf[mi], bhf[nip] + 2);
            }
    }

    const int r_in = lid >> 2;
    const int c_in = (lid & 3) * 2;
#pragma unroll
    for (int mi = 0; mi < 4; mi++) {
#pragma unroll
        for (int ni = 0; ni < 4; ni++) {
            int row0 = brow + wm * 64 + mi * 16 + r_in;
            int col  = bcol + wn * 32 + ni * 8 + c_in;
            size_t i0 = (size_t)row0 * N + col;
            size_t i1 = (size_t)(row0 + 8) * N + col;
            if (epi == 4) {
                *(float2*)&Cf[i0] = make_float2(acc[mi][ni][0], acc[mi][ni][1]);
                *(float2*)&Cf[i1] = make_float2(acc[mi][ni][2], acc[mi][ni][3]);
            } else {
                float2 bv = *(const float2*)&bias[col];
                float v[4];
                v[0] = acc[mi][ni][0] + bv.x;
                v[1] = acc[mi][ni][1] + bv.y;
                v[2] = acc[mi][ni][2] + bv.x;
                v[3] = acc[mi][ni][3] + bv.y;
                if (epi == 1) {
#pragma unroll
                    for (int e = 0; e < 4; e++)
                        v[e] = 0.5f * v[e] * (1.f + erff(v[e] * 0.70710678118654752f));
                }
                __nv_bfloat16 h0,l0,h1,l1;
                split2(v[0], h0, l0); split2(v[1], h1, l1);
                *(__nv_bfloat162*)&Ch[i0] = __nv_bfloat162(h0, h1);
                *(__nv_bfloat162*)&Cl[i0] = __nv_bfloat162(l0, l1);
                split2(v[2], h0, l0); split2(v[3], h1, l1);
                *(__nv_bfloat162*)&Ch[i1] = __nv_bfloat162(h0, h1);
                *(__nv_bfloat162*)&Cl[i1] = __nv_bfloat162(l0, l1);
            }
        }
    }
}

// ======================= HMMA flash attention ================================
#define AP_B    144
#define KV_PART (64 * AP_B)
#define ATT_SMEM (8 * KV_PART)

__global__ __launch_bounds__(256)
void attention_hmma_kernel(const __nv_bfloat16* __restrict__ QKVh,
                           const __nv_bfloat16* __restrict__ QKVl,
                           __nv_bfloat16* __restrict__ Oh, __nv_bfloat16* __restrict__ Ol)
{
    extern __shared__ char smem[];
    const uint32_t sbase = smem_to_u32(smem);
    const int tid = threadIdx.x, wid = tid >> 5, lid = tid & 31;
    const int qt = blockIdx.x, bh = blockIdx.y;
    const int b_ = bh >> 4, h_ = bh & 15;
    const int qrow0 = b_ * SEQ + qt * 128;
    const int krow0 = b_ * SEQ;
    const size_t LDQ = QKV_N;

    {
        const __nv_bfloat16* srcs[2] = { QKVh, QKVl };
#pragma unroll
        for (int t = 0; t < 8; t++) {
            int i = tid + t * 256;
            int part = i >> 10, j = i & 1023, r = j >> 3, c = j & 7;
            cp_async16(sbase + part * (2 * KV_PART) + r * AP_B + c * 16,
                       srcs[part] + (size_t)(qrow0 + r) * LDQ + h_ * 64 + c * 8);
        }
        CP_COMMIT();
    }
    CP_WAIT(0);
    __syncthreads();

    uint32_t aQh[4][4], aQl[4][4];
    {
        const int arow = lid & 15, akof = (lid >> 4) * 8;
#pragma unroll
        for (int ks = 0; ks < 4; ks++) {
            uint32_t off = (wid * 16 + arow) * AP_B + (ks * 16 + akof) * 2;
            ldm_x4(aQh[ks], sbase + off);
            ldm_x4(aQl[ks], sbase + 2 * KV_PART + off);
        }
    }
    __syncthreads();

    auto load_kv = [&](int kt, int s) {
        const __nv_bfloat16* srcs[4] = { QKVh, QKVl, QKVh, QKVl };
        const int coff[4] = { 1024, 1024, 2048, 2048 };
#pragma unroll
        for (int t = 0; t < 8; t++) {
            int i = tid + t * 256;
            int part = i >> 9, j = i & 511, r = j >> 3, c = j & 7;
            cp_async16(sbase + s * (4 * KV_PART) + part * KV_PART + r * AP_B + c * 16,
                       srcs[part] + (size_t)(krow0 + kt * 64 + r) * LDQ + coff[part] + h_ * 64 + c * 8);
        }
        CP_COMMIT();
    };
    load_kv(0, 0);

    float m0 = -INFINITY, m1 = -INFINITY, l0 = 0.f, l1 = 0.f;
    float oA[8][4];
#pragma unroll
    for (int ni = 0; ni < 8; ni++)
#pragma unroll
        for (int e = 0; e < 4; e++) oA[ni][e] = 0.f;

    const int bkey = (lid & 7) + 8 * (lid >> 4);
    const int bkof = ((lid >> 3) & 1) * 8;
    const int vkey = (lid & 7) + 8 * ((lid >> 3) & 1);
    const int vdh  = (lid >> 4) * 8;

    for (int kt = 0; kt < 32; kt++) {
        CP_WAIT(0);
        __syncthreads();
        if (kt < 31) load_kv(kt + 1, (kt + 1) & 1);
        const uint32_t kb = sbase + (kt & 1) * (4 * KV_PART);

        float sc[8][4];
#pragma unroll
        for (int ni = 0; ni < 8; ni++)
#pragma unroll
            for (int e = 0; e < 4; e++) sc[ni][e] = 0.f;

#pragma unroll
        for (int ks = 0; ks < 4; ks++) {
            uint32_t bh4[4][4], bl4[4][4];
#pragma unroll
            for (int nip = 0; nip < 4; nip++) {
                uint32_t off = (nip * 16 + bkey) * AP_B + (ks * 16 + bkof) * 2;
                ldm_x4(bh4[nip], kb + off);
                ldm_x4(bl4[nip], kb + KV_PART + off);
            }
#pragma unroll
            for (int nip = 0; nip < 4; nip++) {
                mma_bf16(sc[2*nip],   aQh[ks], bh4[nip]);
                mma_bf16(sc[2*nip+1], aQh[ks], bh4[nip] + 2);
            }
#pragma unroll
            for (int nip = 0; nip < 4; nip++) {
                mma_bf16(sc[2*nip],   aQh[ks], bl4[nip]);
                mma_bf16(sc[2*nip+1], aQh[ks], bl4[nip] + 2);
            }
#pragma unroll
            for (int nip = 0; nip < 4; nip++) {
                mma_bf16(sc[2*nip],   aQl[ks], bh4[nip]);
                mma_bf16(sc[2*nip+1], aQl[ks], bh4[nip] + 2);
            }
        }

        float mx0 = -INFINITY, mx1 = -INFINITY;
#pragma unroll
        for (int ni = 0; ni < 8; ni++) {
#pragma unroll
            for (int e = 0; e < 4; e++) sc[ni][e] *= 0.125f;
            mx0 = fmaxf(mx0, fmaxf(sc[ni][0], sc[ni][1]));
            mx1 = fmaxf(mx1, fmaxf(sc[ni][2], sc[ni][3]));
        }
        mx0 = fmaxf(mx0, __shfl_xor_sync(0xffffffffu, mx0, 1));
        mx0 = fmaxf(mx0, __shfl_xor_sync(0xffffffffu, mx0, 2));
        mx1 = fmaxf(mx1, __shfl_xor_sync(0xffffffffu, mx1, 1));
        mx1 = fmaxf(mx1, __shfl_xor_sync(0xffffffffu, mx1, 2));
        float mn0 = fmaxf(m0, mx0), mn1 = fmaxf(m1, mx1);
        float f0 = __expf(m0 - mn0), f1 = __expf(m1 - mn1);
        float r0 = 0.f, r1 = 0.f;
#pragma unroll
        for (int ni = 0; ni < 8; ni++) {
            sc[ni][0] = __expf(sc[ni][0] - mn0);
            sc[ni][1] = __expf(sc[ni][1] - mn0);
            sc[ni][2] = __expf(sc[ni][2] - mn1);
            sc[ni][3] = __expf(sc[ni][3] - mn1);
            r0 += sc[ni][0] + sc[ni][1];
            r1 += sc[ni][2] + sc[ni][3];
        }
        r0 += __shfl_xor_sync(0xffffffffu, r0, 1);
        r0 += __shfl_xor_sync(0xffffffffu, r0, 2);
        r1 += __shfl_xor_sync(0xffffffffu, r1, 1);
        r1 += __shfl_xor_sync(0xffffffffu, r1, 2);
        l0 = l0 * f0 + r0;  l1 = l1 * f1 + r1;
        m0 = mn0;           m1 = mn1;
#pragma unroll
        for (int ni = 0; ni < 8; ni++) {
            oA[ni][0] *= f0; oA[ni][1] *= f0;
            oA[ni][2] *= f1; oA[ni][3] *= f1;
        }

#pragma unroll
        for (int ks = 0; ks < 4; ks++) {
            uint32_t ah[4], al[4];
            {
                __nv_bfloat16 h0,l0b,h1,l1b;
                split2(sc[2*ks][0],h0,l0b);   split2(sc[2*ks][1],h1,l1b);   ah[0]=pk(h0,h1); al[0]=pk(l0b,l1b);
                split2(sc[2*ks][2],h0,l0b);   split2(sc[2*ks][3],h1,l1b);   ah[1]=pk(h0,h1); al[1]=pk(l0b,l1b);
                split2(sc[2*ks+1][0],h0,l0b); split2(sc[2*ks+1][1],h1,l1b); ah[2]=pk(h0,h1); al[2]=pk(l0b,l1b);
                split2(sc[2*ks+1][2],h0,l0b); split2(sc[2*ks+1][3],h1,l1b); ah[3]=pk(h0,h1); al[3]=pk(l0b,l1b);
            }
            uint32_t vh4[4][4], vl4[4][4];
#pragma unroll
            for (int nip = 0; nip < 4; nip++) {
                uint32_t off = (ks * 16 + vkey) * AP_B + (nip * 16 + vdh) * 2;
                ldm_x4_t(vh4[nip], kb + 2 * KV_PART + off);
                ldm_x4_t(vl4[nip], kb + 3 * KV_PART + off);
            }
#pragma unroll
            for (int nip = 0; nip < 4; nip++) {
                mma_bf16(oA[2*nip],   ah, vh4[nip]);
                mma_bf16(oA[2*nip+1], ah, vh4[nip] + 2);
            }
#pragma unroll
            for (int nip = 0; nip < 4; nip++) {
                mma_bf16(oA[2*nip],   ah, vl4[nip]);
                mma_bf16(oA[2*nip+1], ah, vl4[nip] + 2);
            }
#pragma unroll
            for (int nip = 0; nip < 4; nip++) {
                mma_bf16(oA[2*nip],   al, vh4[nip]);
                mma_bf16(oA[2*nip+1], al, vh4[nip] + 2);
            }
        }
    }

    const float inv0 = 1.f / l0, inv1 = 1.f / l1;
    const int row0 = qrow0 + wid * 16 + (lid >> 2);
    const int colb = h_ * 64 + (lid & 3) * 2;
#pragma unroll
    for (int ni = 0; ni < 8; ni++) {
        int col = colb + ni * 8;
        __nv_bfloat16 h0,lo0,h1,lo1;
        split2(oA[ni][0] * inv0, h0, lo0);
        split2(oA[ni][1] * inv0, h1, lo1);
        size_t i0 = (size_t)row0 * D_MODEL + col;
        *(__nv_bfloat162*)&Oh[i0] = __nv_bfloat162(h0, h1);
        *(__nv_bfloat162*)&Ol[i0] = __nv_bfloat162(lo0, lo1);
        split2(oA[ni][2] * inv1, h0, lo0);
        split2(oA[ni][3] * inv1, h1, lo1);
        size_t i1 = (size_t)(row0 + 8) * D_MODEL + col;
        *(__nv_bfloat162*)&Oh[i1] = __nv_bfloat162(h0, h1);
        *(__nv_bfloat162*)&Ol[i1] = __nv_bfloat162(lo0, lo1);
    }
}

// ======================= fused split-K reduce + layernorm ====================
__global__ void layernorm_sum_kernel(const float* __restrict__ P0, const float* __restrict__ P1,
                                     const float* __restrict__ bias, const float* __restrict__ Res,
                                     const float* __restrict__ g, const float* __restrict__ be,
                                     float* __restrict__ out,
                                     __nv_bfloat16* __restrict__ oh, __nv_bfloat16* __restrict__ ol,
                                     int transpose_out)
{
    __shared__ float rs[8], rq[8];
    const int row = blockIdx.x;
    const int tid = threadIdx.x;

    float4 a = ((const float4*)(P0 + (size_t)row * D_MODEL))[tid];
    float4 b = ((const float4*)(P1 + (size_t)row * D_MODEL))[tid];
    float4 r = ((const float4*)(Res + (size_t)row * D_MODEL))[tid];
    float4 bb = ((const float4*)bias)[tid];
    float4 v;
    v.x = a.x + b.x + bb.x + r.x;
    v.y = a.y + b.y + bb.y + r.y;
    v.z = a.z + b.z + bb.z + r.z;
    v.w = a.w + b.w + bb.w + r.w;

    float s = v.x + v.y + v.z + v.w;
    float q = v.x*v.x + v.y*v.y + v.z*v.z + v.w*v.w;
#pragma unroll
    for (int o = 16; o >= 1; o >>= 1) {
        s += __shfl_xor_sync(0xffffffffu, s, o);
        q += __shfl_xor_sync(0xffffffffu, q, o);
    }
    if ((tid & 31) == 0) { rs[tid >> 5] = s; rq[tid >> 5] = q; }
    __syncthreads();
    s = 0.f; q = 0.f;
#pragma unroll
    for (int i = 0; i < 8; i++) { s += rs[i]; q += rq[i]; }

    float mean = s * (1.f / D_MODEL);
    float var  = q * (1.f / D_MODEL) - mean * mean;
    float rstd = rsqrtf(var + EPS);

    float4 g4 = ((const float4*)g)[tid];
    float4 b4 = ((const float4*)be)[tid];
    float4 o4;
    o4.x = (v.x - mean) * rstd * g4.x + b4.x;
    o4.y = (v.y - mean) * rstd * g4.y + b4.y;
    o4.z = (v.z - mean) * rstd * g4.z + b4.z;
    o4.w = (v.w - mean) * rstd * g4.w + b4.w;

    size_t orow = row;
    if (transpose_out) {
        int b_ = row >> 11;
        int s_ = row & 2047;
        orow = (size_t)s_ * BATCH + b_;
    }
    ((float4*)(out + orow * D_MODEL))[tid] = o4;

    if (oh) {
        __nv_bfloat16 h0,l0,h1,l1,h2,l2,h3,l3;
        split2(o4.x,h0,l0); split2(o4.y,h1,l1); split2(o4.z,h2,l2); split2(o4.w,h3,l3);
        size_t o = (size_t)row * D_MODEL + tid * 4;
        *(__nv_bfloat162*)(oh + o)     = __nv_bfloat162(h0, h1);
        *(__nv_bfloat162*)(oh + o + 2) = __nv_bfloat162(h2, h3);
        *(__nv_bfloat162*)(ol + o)     = __nv_bfloat162(l0, l1);
        *(__nv_bfloat162*)(ol + o + 2) = __nv_bfloat162(l2, l3);
    }
}

// ======================= launch =============================================
extern "C" void kernel_launch(void* const* d_in, const int* in_sizes, int n_in,
                              void* d_out, int out_size)
{
    const float* x   = (const float*)d_in[0];
    const float* Wq  = (const float*)d_in[1];
    const float* bq  = (const float*)d_in[2];
    const float* Wk  = (const float*)d_in[3];
    const float* bk  = (const float*)d_in[4];
    const float* Wv  = (const float*)d_in[5];
    const float* bv  = (const float*)d_in[6];
    const float* Wo  = (const float*)d_in[7];
    const float* bo  = (const float*)d_in[8];
    const float* W1  = (const float*)d_in[9];
    const float* b1  = (const float*)d_in[10];
    const float* W2  = (const float*)d_in[11];
    const float* b2  = (const float*)d_in[12];
    const float* g1  = (const float*)d_in[13];
    const float* be1 = (const float*)d_in[14];
    const float* g2  = (const float*)d_in[15];
    const float* be2 = (const float*)d_in[16];
    float* out = (float*)d_out;

    float *XB, *P0, *P1, *X1, *bqkv;
    __nv_bfloat16 *XBh, *XBl, *QKVh, *QKVl, *CTXh, *CTXl, *X1h, *X1l, *Hh, *Hl;
    __nv_bfloat16 *Wqkvth, *Wqkvtl, *Woth, *Wotl, *W1th, *W1tl, *W2th, *W2tl;
    cudaGetSymbolAddress((void**)&XB,   g_XB);
    cudaGetSymbolAddress((void**)&XBh,  g_XBh);
    cudaGetSymbolAddress((void**)&XBl,  g_XBl);
    cudaGetSymbolAddress((void**)&QKVh, g_QKVh);
    cudaGetSymbolAddress((void**)&QKVl, g_QKVl);
    cudaGetSymbolAddress((void**)&CTXh, g_CTXh);
    cudaGetSymbolAddress((void**)&CTXl, g_CTXl);
    cudaGetSymbolAddress((void**)&P0,   g_P0);
    cudaGetSymbolAddress((void**)&P1,   g_P1);
    cudaGetSymbolAddress((void**)&X1,   g_X1);
    cudaGetSymbolAddress((void**)&X1h,  g_X1h);
    cudaGetSymbolAddress((void**)&X1l,  g_X1l);
    cudaGetSymbolAddress((void**)&Hh,   g_Hh);
    cudaGetSymbolAddress((void**)&Hl,   g_Hl);
    cudaGetSymbolAddress((void**)&Wqkvth, g_Wqkvth);
    cudaGetSymbolAddress((void**)&Wqkvtl, g_Wqkvtl);
    cudaGetSymbolAddress((void**)&Woth, g_Woth);
    cudaGetSymbolAddress((void**)&Wotl, g_Wotl);
    cudaGetSymbolAddress((void**)&W1th, g_W1th);
    cudaGetSymbolAddress((void**)&W1tl, g_W1tl);
    cudaGetSymbolAddress((void**)&W2th, g_W2th);
    cudaGetSymbolAddress((void**)&W2tl, g_W2tl);
    cudaGetSymbolAddress((void**)&bqkv, g_bqkv);

    cudaFuncSetAttribute(gemm_hmma_kernel, cudaFuncAttributeMaxDynamicSharedMemorySize, GEMM_SMEM);
    cudaFuncSetAttribute(attention_hmma_kernel, cudaFuncAttributeMaxDynamicSharedMemorySize, ATT_SMEM);

    // fused prep (input transpose + 6 weight transposes + bias concat)
    prep_all_kernel<<<16396, 256>>>(
        x, Wq, Wk, Wv, Wo, W1, W2, bq, bk, bv,
        XB, XBh, XBl,
        Wqkvth, Wqkvtl, Woth, Wotl, W1th, W1tl, W2th, W2tl, bqkv);

    // fused QKV -> bf16 hi/lo (epi 3)
    gemm_hmma_kernel<<<dim3(QKV_N/128, NTOK/128, 1), 256, GEMM_SMEM>>>(
        XBh, XBl, Wqkvth, Wqkvtl, bqkv, nullptr, nullptr, QKVh, QKVl,
        D_MODEL, D_MODEL, QKV_N, 3);

    // HMMA flash attention -> CTX hi/lo
    attention_hmma_kernel<<<dim3(SEQ/128, BATCH*NHEAD), 256, ATT_SMEM>>>(QKVh, QKVl, CTXh, CTXl);

    // O-proj split-K=2 ; fused reduce+bias+res+LN1 -> X1 (+hi/lo)
    gemm_hmma_kernel<<<dim3(D_MODEL/128, NTOK/128, 2), 256, GEMM_SMEM>>>(
        CTXh, CTXl, Woth, Wotl, nullptr, P0, P1, nullptr, nullptr,
        D_MODEL/2, D_MODEL, D_MODEL, 4);
    layernorm_sum_kernel<<<NTOK, 256>>>(P0, P1, bo, XB, g1, be1, X1, X1h, X1l, 0);

    // FFN1 (+GELU) -> H hi/lo (epi 1)
    gemm_hmma_kernel<<<dim3(D_FF/128, NTOK/128, 1), 256, GEMM_SMEM>>>(
        X1h, X1l, W1th, W1tl, b1, nullptr, nullptr, Hh, Hl,
        D_MODEL, D_MODEL, D_FF, 1);

    // FFN2 split-K=2 ; fused reduce+bias+res+LN2 -> out (transposed)
    gemm_hmma_kernel<<<dim3(D_MODEL/128, NTOK/128, 2), 256, GEMM_SMEM>>>(
        Hh, Hl, W2th, W2tl, nullptr, P0, P1, nullptr, nullptr,
        D_FF/2, D_FF, D_MODEL, 4);
    layernorm_sum_kernel<<<NTOK, 256>>>(P0, P1, b2, X1, g2, be2, out, nullptr, nullptr, 1);
}

// round 14
// speedup vs baseline: 1.0904x; 1.0219x over previous
#include <cuda_runtime.h>
#include <cuda_bf16.h>
#include <cuda.h>
#include <math.h>
#include <stdint.h>

#define D_MODEL 1024
#define NHEAD   16
#define DH      64
#define D_FF    4096
#define SEQ     2048
#define BATCH   2
#define NTOK    (SEQ * BATCH)
#define EPS     1e-5f
#define QKV_N   (3 * D_MODEL)   // 3072

// ======================= helpers ============================================
__device__ __forceinline__ uint32_t smem_to_u32(const void* p) {
    uint32_t a;
    asm("{ .reg .u64 t; cvta.to.shared.u64 t, %1; cvt.u32.u64 %0, t; }" : "=r"(a) : "l"(p));
    return a;
}
__device__ __forceinline__ void cp_async16(uint32_t dst, const void* src) {
    asm volatile("cp.async.cg.shared.global [%0], [%1], 16;" :: "r"(dst), "l"(src) : "memory");
}
#define CP_COMMIT() asm volatile("cp.async.commit_group;" ::: "memory")
#define CP_WAIT(n)  asm volatile("cp.async.wait_group %0;" :: "n"(n) : "memory")

__device__ __forceinline__ void ldm_x4(uint32_t* r, uint32_t addr) {
    asm volatile("ldmatrix.sync.aligned.m8n8.x4.shared.b16 {%0,%1,%2,%3}, [%4];"
        : "=r"(r[0]), "=r"(r[1]), "=r"(r[2]), "=r"(r[3]) : "r"(addr));
}
__device__ __forceinline__ void ldm_x4_t(uint32_t* r, uint32_t addr) {
    asm volatile("ldmatrix.sync.aligned.m8n8.x4.trans.shared.b16 {%0,%1,%2,%3}, [%4];"
        : "=r"(r[0]), "=r"(r[1]), "=r"(r[2]), "=r"(r[3]) : "r"(addr));
}
__device__ __forceinline__ void mma_bf16(float* d, const uint32_t* a, const uint32_t* b) {
    asm volatile("mma.sync.aligned.m16n8k16.row.col.f32.bf16.bf16.f32 "
        "{%0,%1,%2,%3}, {%4,%5,%6,%7}, {%8,%9}, {%0,%1,%2,%3};"
        : "+f"(d[0]), "+f"(d[1]), "+f"(d[2]), "+f"(d[3])
        : "r"(a[0]), "r"(a[1]), "r"(a[2]), "r"(a[3]), "r"(b[0]), "r"(b[1]));
}
__device__ __forceinline__ void split2(float x, __nv_bfloat16& h, __nv_bfloat16& l) {
    h = __float2bfloat16_rn(x);
    l = __float2bfloat16_rn(x - __bfloat162float(h));
}
__device__ __forceinline__ uint32_t pk(__nv_bfloat16 a, __nv_bfloat16 b) {
    __nv_bfloat162 t(a, b);
    return *reinterpret_cast<uint32_t*>(&t);
}

// ======================= scratch ============================================
__device__ float          g_XB  [NTOK * D_MODEL];
__device__ __nv_bfloat16  g_XBh [NTOK * D_MODEL];
__device__ __nv_bfloat16  g_XBl [NTOK * D_MODEL];
__device__ __nv_bfloat16  g_QKVh[NTOK * QKV_N];
__device__ __nv_bfloat16  g_QKVl[NTOK * QKV_N];
__device__ __nv_bfloat16  g_CTXh[NTOK * D_MODEL];
__device__ __nv_bfloat16  g_CTXl[NTOK * D_MODEL];
__device__ float          g_P0  [NTOK * D_MODEL];
__device__ float          g_P1  [NTOK * D_MODEL];
__device__ float          g_X1  [NTOK * D_MODEL];
__device__ __nv_bfloat16  g_X1h [NTOK * D_MODEL];
__device__ __nv_bfloat16  g_X1l [NTOK * D_MODEL];
__device__ __nv_bfloat16  g_Hh  [NTOK * D_FF];
__device__ __nv_bfloat16  g_Hl  [NTOK * D_FF];
__device__ __nv_bfloat16  g_Wqkvth[QKV_N * D_MODEL];
__device__ __nv_bfloat16  g_Wqkvtl[QKV_N * D_MODEL];
__device__ __nv_bfloat16  g_Woth[D_MODEL * D_MODEL];
__device__ __nv_bfloat16  g_Wotl[D_MODEL * D_MODEL];
__device__ __nv_bfloat16  g_W1th[D_FF * D_MODEL];
__device__ __nv_bfloat16  g_W1tl[D_FF * D_MODEL];
__device__ __nv_bfloat16  g_W2th[D_MODEL * D_FF];
__device__ __nv_bfloat16  g_W2tl[D_MODEL * D_FF];
__device__ float          g_bqkv[QKV_N];

// ======================= fused prep kernel ===================================
__global__ void prep_all_kernel(
    const float* __restrict__ x,
    const float* __restrict__ Wq, const float* __restrict__ Wk,
    const float* __restrict__ Wv, const float* __restrict__ Wo,
    const float* __restrict__ W1, const float* __restrict__ W2,
    const float* __restrict__ bq, const float* __restrict__ bk, const float* __restrict__ bv,
    float* __restrict__ xb, __nv_bfloat16* __restrict__ xh, __nv_bfloat16* __restrict__ xl,
    __nv_bfloat16* __restrict__ Wqkvth, __nv_bfloat16* __restrict__ Wqkvtl,
    __nv_bfloat16* __restrict__ Woth,   __nv_bfloat16* __restrict__ Wotl,
    __nv_bfloat16* __restrict__ W1th,   __nv_bfloat16* __restrict__ W1tl,
    __nv_bfloat16* __restrict__ W2th,   __nv_bfloat16* __restrict__ W2tl,
    float* __restrict__ bqkv)
{
    __shared__ float t[32][33];
    const int blk = blockIdx.x;
    const int tid = threadIdx.x;

    if (blk >= 16384) {                      // ---- bias concat ----
        int i = (blk - 16384) * 256 + tid;
        if (i < QKV_N) {
            const float* s = (i < 1024) ? bq : (i < 2048) ? bk : bv;
            bqkv[i] = s[i & 1023];
        }
        return;
    }
    if (blk >= 12288) {                      // ---- input transpose + split ----
        int idx = (blk - 12288) * 256 + tid;
        int r  = idx >> 8;
        int c4 = idx & 255;
        int b_ = r / SEQ;
        int s_ = r - b_ * SEQ;
        float4 v = ((const float4*)x)[(size_t)(s_ * BATCH + b_) * 256 + c4];
        ((float4*)xb)[idx] = v;
        __nv_bfloat16 h0,l0,h1,l1,h2,l2,h3,l3;
        split2(v.x,h0,l0); split2(v.y,h1,l1); split2(v.z,h2,l2); split2(v.w,h3,l3);
        __nv_bfloat162* ph = (__nv_bfloat162*)(xh + (size_t)idx * 4);
        __nv_bfloat162* pl = (__nv_bfloat162*)(xl + (size_t)idx * 4);
        ph[0] = __nv_bfloat162(h0, h1); ph[1] = __nv_bfloat162(h2, h3);
        pl[0] = __nv_bfloat162(l0, l1); pl[1] = __nv_bfloat162(l2, l3);
        return;
    }

    // ---- weight transpose + split ----
    const float* W; __nv_bfloat16 *Oh, *Ol;
    int K, N, bx, by;
    if (blk < 4096) {
        int m = blk >> 10;
        int j = blk & 1023;
        K = D_MODEL; N = D_MODEL;
        bx = j & 31; by = j >> 5;
        if (m == 0)      { W = Wq; Oh = Wqkvth;                                Ol = Wqkvtl; }
        else if (m == 1) { W = Wk; Oh = Wqkvth + (size_t)D_MODEL*D_MODEL;      Ol = Wqkvtl + (size_t)D_MODEL*D_MODEL; }
        else if (m == 2) { W = Wv; Oh = Wqkvth + (size_t)2*D_MODEL*D_MODEL;    Ol = Wqkvtl + (size_t)2*D_MODEL*D_MODEL; }
        else             { W = Wo; Oh = Woth;                                  Ol = Wotl; }
    } else if (blk < 8192) {
        int j = blk - 4096;
        K = D_MODEL; N = D_FF;
        bx = j & 127; by = j >> 7;
        W = W1; Oh = W1th; Ol = W1tl;
    } else {
        int j = blk - 8192;
        K = D_FF; N = D_MODEL;
        bx = j & 31; by = j >> 5;
        W = W2; Oh = W2th; Ol = W2tl;
    }
    int n0 = bx * 32, k0 = by * 32;
    int tx = tid & 31, ty = tid >> 5;
#pragma unroll
    for (int i = 0; i < 4; i++)
        t[ty + 8*i][tx] = W[(size_t)(k0 + ty + 8*i) * N + n0 + tx];
    __syncthreads();
#pragma unroll
    for (int i = 0; i < 4; i++) {
        float v = t[tx][ty + 8*i];
        __nv_bfloat16 h, l; split2(v, h, l);
        size_t o = (size_t)(n0 + ty + 8*i) * K + k0 + tx;
        Oh[o] = h; Ol[o] = l;
    }
}

// ======================= HMMA bf16x3 GEMM (R11 geometry) =====================
#define GK        32
#define ROWB      80
#define PARTB     (128 * ROWB)
#define STAGEB    (4 * PARTB)
#define GEMM_SMEM (2 * STAGEB)

__global__ __launch_bounds__(256, 2)
void gemm_hmma_kernel(const __nv_bfloat16* __restrict__ Ah, const __nv_bfloat16* __restrict__ Al,
                      const __nv_bfloat16* __restrict__ Bth, const __nv_bfloat16* __restrict__ Btl,
                      const float* __restrict__ bias,
                      float* __restrict__ Cf0, float* __restrict__ Cf1,
                      __nv_bfloat16* __restrict__ Ch, __nv_bfloat16* __restrict__ Cl,
                      int Klen, int LDK, int N, int epi)
{
    extern __shared__ char smem[];
    const uint32_t sbase = smem_to_u32(smem);

    const int tid = threadIdx.x;
    const int wid = tid >> 5;
    const int lid = tid & 31;
    const int wm = wid >> 2;
    const int wn = wid & 3;
    const int brow = blockIdx.y * 128;
    const int bcol = blockIdx.x * 128;
    const int kz = blockIdx.z;
    const int NC = Klen / GK;

    const size_t kofs = (size_t)kz * Klen;
    Ah += kofs; Al += kofs; Bth += kofs; Btl += kofs;
    float* Cf = kz ? Cf1 : Cf0;

    float acc[4][4][4];
#pragma unroll
    for (int mi = 0; mi < 4; mi++)
#pragma unroll
        for (int ni = 0; ni < 4; ni++)
#pragma unroll
            for (int e = 0; e < 4; e++) acc[mi][ni][e] = 0.f;

    auto load_chunk = [&](int kc, int s) {
        const int kb = kc * GK;
        const __nv_bfloat16* srcs[4] = { Ah, Al, Bth, Btl };
#pragma unroll
        for (int p = 0; p < 8; p++) {
            int i = tid + p * 256;
            int part = i >> 9;
            int j = i & 511;
            int r = j >> 2, c = j & 3;
            int grow = ((part < 2) ? brow : bcol) + r;
            const __nv_bfloat16* src = srcs[part] + (size_t)grow * LDK + kb + c * 8;
            cp_async16(sbase + s * STAGEB + part * PARTB + r * ROWB + c * 16, src);
        }
        CP_COMMIT();
    };

    const int a_row = lid & 15;
    const int a_kof = (lid >> 4) * 8;
    const int bkey  = (lid & 7) + 8 * (lid >> 4);
    const int bkof  = ((lid >> 3) & 1) * 8;

    load_chunk(0, 0);

    for (int kc = 0; kc < NC; kc++) {
        CP_WAIT(0);
        __syncthreads();

        const uint32_t st = sbase + (kc & 1) * STAGEB;
        const uint32_t ah_b = st;
        const uint32_t al_b = st + PARTB;
        const uint32_t bh_b = st + 2 * PARTB;
        const uint32_t bl_b = st + 3 * PARTB;

        // ---- ks = 0: LDSM first, then next-chunk cp.async ----
        uint32_t ahf[4][4], alf[4][4], bhf[2][4], blf[2][4];
#pragma unroll
        for (int mi = 0; mi < 4; mi++) {
            int row = wm * 64 + mi * 16 + a_row;
            uint32_t off = row * ROWB + a_kof * 2;
            ldm_x4(ahf[mi], ah_b + off);
            ldm_x4(alf[mi], al_b + off);
        }
#pragma unroll
        for (int nip = 0; nip < 2; nip++) {
            uint32_t off = (wn * 32 + nip * 16 + bkey) * ROWB + bkof * 2;
            ldm_x4(bhf[nip], bh_b + off);
            ldm_x4(blf[nip], bl_b + off);
        }
        if (kc + 1 < NC) load_chunk(kc + 1, (kc + 1) & 1);

#pragma unroll
        for (int mi = 0; mi < 4; mi++)
#pragma unroll
            for (int nip = 0; nip < 2; nip++) {
                mma_bf16(acc[mi][2*nip],   ahf[mi], bhf[nip]);
                mma_bf16(acc[mi][2*nip+1], ahf[mi], bhf[nip] + 2);
                mma_bf16(acc[mi][2*nip],   ahf[mi], blf[nip]);
                mma_bf16(acc[mi][2*nip+1], ahf[mi], blf[nip] + 2);
                mma_bf16(acc[mi][2*nip],   alf[mi], bhf[nip]);
                mma_bf16(acc[mi][2*nip+1], alf[mi], bhf[nip] + 2);
            }

        // ---- ks = 1 ----
#pragma unroll
        for (int mi = 0; mi < 4; mi++) {
            int row = wm * 64 + mi * 16 + a_row;
            uint32_t off = row * ROWB + (16 + a_kof) * 2;
            ldm_x4(ahf[mi], ah_b + off);
            ldm_x4(alf[mi], al_b + off);
        }
#pragma unroll
        for (int nip = 0; nip < 2; nip++) {
            uint32_t off = (wn * 32 + nip * 16 + bkey) * ROWB + (16 + bkof) * 2;
            ldm_x4(bhf[nip], bh_b + off);
            ldm_x4(blf[nip], bl_b + off);
        }
#pragma unroll
        for (int mi = 0; mi < 4; mi++)
#pragma unroll
            for (int nip = 0; nip < 2; nip++) {
                mma_bf16(acc[mi][2*nip],   ahf[mi], bhf[nip]);
                mma_bf16(acc[mi][2*nip+1], ahf[mi], bhf[nip] + 2);
                mma_bf16(acc[mi][2*nip],   ahf[mi], blf[nip]);
                mma_bf16(acc[mi][2*nip+1], ahf[mi], blf[nip] + 2);
                mma_bf16(acc[mi][2*nip],   alf[mi], bhf[nip]);
                mma_bf16(acc[mi][2*nip+1], alf[mi], bhf[nip] + 2);
            }
    }

    const int r_in = lid >> 2;
    const int c_in = (lid & 3) * 2;
#pragma unroll
    for (int mi = 0; mi < 4; mi++) {
#pragma unroll
        for (int ni = 0; ni < 4; ni++) {
            int row0 = brow + wm * 64 + mi * 16 + r_in;
            int col  = bcol + wn * 32 + ni * 8 + c_in;
            size_t i0 = (size_t)row0 * N + col;
            size_t i1 = (size_t)(row0 + 8) * N + col;
            if (epi == 4) {
                *(float2*)&Cf[i0] = make_float2(acc[mi][ni][0], acc[mi][ni][1]);
                *(float2*)&Cf[i1] = make_float2(acc[mi][ni][2], acc[mi][ni][3]);
            } else {
                float2 bv = *(const float2*)&bias[col];
                float v[4];
                v[0] = acc[mi][ni][0] + bv.x;
                v[1] = acc[mi][ni][1] + bv.y;
                v[2] = acc[mi][ni][2] + bv.x;
                v[3] = acc[mi][ni][3] + bv.y;
                if (epi == 1) {
#pragma unroll
                    for (int e = 0; e < 4; e++)
                        v[e] = 0.5f * v[e] * (1.f + erff(v[e] * 0.70710678118654752f));
                }
                __nv_bfloat16 h0,l0,h1,l1;
                split2(v[0], h0, l0); split2(v[1], h1, l1);
                *(__nv_bfloat162*)&Ch[i0] = __nv_bfloat162(h0, h1);
                *(__nv_bfloat162*)&Cl[i0] = __nv_bfloat162(l0, l1);
                split2(v[2], h0, l0); split2(v[3], h1, l1);
                *(__nv_bfloat162*)&Ch[i1] = __nv_bfloat162(h0, h1);
                *(__nv_bfloat162*)&Cl[i1] = __nv_bfloat162(l0, l1);
            }
        }
    }
}

// ======================= HMMA flash attention (2 CTA/SM) =====================
// Dedicated Q smem (Q frags re-read per use -> low registers); regs capped 128.
#define AP_B    144
#define Q_PART  (128 * AP_B)                // 18432
#define KV_PART (64 * AP_B)                 // 9216
#define ATT_SMEM (2 * Q_PART + 8 * KV_PART) // 110592 ; 2x = 221184 <= 228KB

__global__ __launch_bounds__(256, 2)
void attention_hmma_kernel(const __nv_bfloat16* __restrict__ QKVh,
                           const __nv_bfloat16* __restrict__ QKVl,
                           __nv_bfloat16* __restrict__ Oh, __nv_bfloat16* __restrict__ Ol)
{
    extern __shared__ char smem[];
    const uint32_t sbase = smem_to_u32(smem);
    const int tid = threadIdx.x, wid = tid >> 5, lid = tid & 31;
    const int qt = blockIdx.x, bh = blockIdx.y;
    const int b_ = bh >> 4, h_ = bh & 15;
    const int qrow0 = b_ * SEQ + qt * 128;
    const int krow0 = b_ * SEQ;
    const size_t LDQ = QKV_N;
    const uint32_t ringb = sbase + 2 * Q_PART;

    // Q hi/lo -> dedicated smem (stays whole kernel)
    {
        const __nv_bfloat16* srcs[2] = { QKVh, QKVl };
#pragma unroll
        for (int t = 0; t < 8; t++) {
            int i = tid + t * 256;
            int part = i >> 10, j = i & 1023, r = j >> 3, c = j & 7;
            cp_async16(sbase + part * Q_PART + r * AP_B + c * 16,
                       srcs[part] + (size_t)(qrow0 + r) * LDQ + h_ * 64 + c * 8);
        }
        CP_COMMIT();
    }
    auto load_kv = [&](int kt, int s) {
        const __nv_bfloat16* srcs[4] = { QKVh, QKVl, QKVh, QKVl };
        const int coff[4] = { 1024, 1024, 2048, 2048 };
#pragma unroll
        for (int t = 0; t < 8; t++) {
            int i = tid + t * 256;
            int part = i >> 9, j = i & 511, r = j >> 3, c = j & 7;
            cp_async16(ringb + s * (4 * KV_PART) + part * KV_PART + r * AP_B + c * 16,
                       srcs[part] + (size_t)(krow0 + kt * 64 + r) * LDQ + coff[part] + h_ * 64 + c * 8);
        }
        CP_COMMIT();
    };
    load_kv(0, 0);

    float m0 = -INFINITY, m1 = -INFINITY, l0 = 0.f, l1 = 0.f;
    float oA[8][4];
#pragma unroll
    for (int ni = 0; ni < 8; ni++)
#pragma unroll
        for (int e = 0; e < 4; e++) oA[ni][e] = 0.f;

    const int arow = lid & 15;
    const int akof = (lid >> 4) * 8;
    const int bkey = (lid & 7) + 8 * (lid >> 4);
    const int bkof = ((lid >> 3) & 1) * 8;
    const int vkey = (lid & 7) + 8 * ((lid >> 3) & 1);
    const int vdh  = (lid >> 4) * 8;

    for (int kt = 0; kt < 32; kt++) {
        CP_WAIT(0);
        __syncthreads();                     // KV tile kt visible (Q visible at kt=0)
        if (kt < 31) load_kv(kt + 1, (kt + 1) & 1);
        const uint32_t kb = ringb + (kt & 1) * (4 * KV_PART);

        float sc[8][4];
#pragma unroll
        for (int ni = 0; ni < 8; ni++)
#pragma unroll
            for (int e = 0; e < 4; e++) sc[ni][e] = 0.f;

#pragma unroll
        for (int ks = 0; ks < 4; ks++) {
            // Q frags from smem (2 LDSM) -- keeps registers low
            uint32_t aQh[4], aQl[4];
            {
                uint32_t qoff = (wid * 16 + arow) * AP_B + (ks * 16 + akof) * 2;
                ldm_x4(aQh, sbase + qoff);
                ldm_x4(aQl, sbase + Q_PART + qoff);
            }
            uint32_t bh4[4][4], bl4[4][4];
#pragma unroll
            for (int nip = 0; nip < 4; nip++) {
                uint32_t off = (nip * 16 + bkey) * AP_B + (ks * 16 + bkof) * 2;
                ldm_x4(bh4[nip], kb + off);
                ldm_x4(bl4[nip], kb + KV_PART + off);
            }
#pragma unroll
            for (int nip = 0; nip < 4; nip++) {
                mma_bf16(sc[2*nip],   aQh, bh4[nip]);
                mma_bf16(sc[2*nip+1], aQh, bh4[nip] + 2);
            }
#pragma unroll
            for (int nip = 0; nip < 4; nip++) {
                mma_bf16(sc[2*nip],   aQh, bl4[nip]);
                mma_bf16(sc[2*nip+1], aQh, bl4[nip] + 2);
            }
#pragma unroll
            for (int nip = 0; nip < 4; nip++) {
                mma_bf16(sc[2*nip],   aQl, bh4[nip]);
                mma_bf16(sc[2*nip+1], aQl, bh4[nip] + 2);
            }
        }

        float mx0 = -INFINITY, mx1 = -INFINITY;
#pragma unroll
        for (int ni = 0; ni < 8; ni++) {
#pragma unroll
            for (int e = 0; e < 4; e++) sc[ni][e] *= 0.125f;
            mx0 = fmaxf(mx0, fmaxf(sc[ni][0], sc[ni][1]));
            mx1 = fmaxf(mx1, fmaxf(sc[ni][2], sc[ni][3]));
        }
        mx0 = fmaxf(mx0, __shfl_xor_sync(0xffffffffu, mx0, 1));
        mx0 = fmaxf(mx0, __shfl_xor_sync(0xffffffffu, mx0, 2));
        mx1 = fmaxf(mx1, __shfl_xor_sync(0xffffffffu, mx1, 1));
        mx1 = fmaxf(mx1, __shfl_xor_sync(0xffffffffu, mx1, 2));
        float mn0 = fmaxf(m0, mx0), mn1 = fmaxf(m1, mx1);
        float f0 = __expf(m0 - mn0), f1 = __expf(m1 - mn1);
        float r0 = 0.f, r1 = 0.f;
#pragma unroll
        for (int ni = 0; ni < 8; ni++) {
            sc[ni][0] = __expf(sc[ni][0] - mn0);
            sc[ni][1] = __expf(sc[ni][1] - mn0);
            sc[ni][2] = __expf(sc[ni][2] - mn1);
            sc[ni][3] = __expf(sc[ni][3] - mn1);
            r0 += sc[ni][0] + sc[ni][1];
            r1 += sc[ni][2] + sc[ni][3];
        }
        r0 += __shfl_xor_sync(0xffffffffu, r0, 1);
        r0 += __shfl_xor_sync(0xffffffffu, r0, 2);
        r1 += __shfl_xor_sync(0xffffffffu, r1, 1);
        r1 += __shfl_xor_sync(0xffffffffu, r1, 2);
        l0 = l0 * f0 + r0;  l1 = l1 * f1 + r1;
        m0 = mn0;           m1 = mn1;
#pragma unroll
        for (int ni = 0; ni < 8; ni++) {
            oA[ni][0] *= f0; oA[ni][1] *= f0;
            oA[ni][2] *= f1; oA[ni][3] *= f1;
        }

#pragma unroll
        for (int ks = 0; ks < 4; ks++) {
            uint32_t ah[4], al[4];
            {
                __nv_bfloat16 h0,l0b,h1,l1b;
                split2(sc[2*ks][0],h0,l0b);   split2(sc[2*ks][1],h1,l1b);   ah[0]=pk(h0,h1); al[0]=pk(l0b,l1b);
                split2(sc[2*ks][2],h0,l0b);   split2(sc[2*ks][3],h1,l1b);   ah[1]=pk(h0,h1); al[1]=pk(l0b,l1b);
                split2(sc[2*ks+1][0],h0,l0b); split2(sc[2*ks+1][1],h1,l1b); ah[2]=pk(h0,h1); al[2]=pk(l0b,l1b);
                split2(sc[2*ks+1][2],h0,l0b); split2(sc[2*ks+1][3],h1,l1b); ah[3]=pk(h0,h1); al[3]=pk(l0b,l1b);
            }
            uint32_t vh4[4][4], vl4[4][4];
#pragma unroll
            for (int nip = 0; nip < 4; nip++) {
                uint32_t off = (ks * 16 + vkey) * AP_B + (nip * 16 + vdh) * 2;
                ldm_x4_t(vh4[nip], kb + 2 * KV_PART + off);
                ldm_x4_t(vl4[nip], kb + 3 * KV_PART + off);
            }
#pragma unroll
            for (int nip = 0; nip < 4; nip++) {
                mma_bf16(oA[2*nip],   ah, vh4[nip]);
                mma_bf16(oA[2*nip+1], ah, vh4[nip] + 2);
            }
#pragma unroll
            for (int nip = 0; nip < 4; nip++) {
                mma_bf16(oA[2*nip],   ah, vl4[nip]);
                mma_bf16(oA[2*nip+1], ah, vl4[nip] + 2);
            }
#pragma unroll
            for (int nip = 0; nip < 4; nip++) {
                mma_bf16(oA[2*nip],   al, vh4[nip]);
                mma_bf16(oA[2*nip+1], al, vh4[nip] + 2);
            }
        }
    }

    const float inv0 = 1.f / l0, inv1 = 1.f / l1;
    const int row0 = qrow0 + wid * 16 + (lid >> 2);
    const int colb = h_ * 64 + (lid & 3) * 2;
#pragma unroll
    for (int ni = 0; ni < 8; ni++) {
        int col = colb + ni * 8;
        __nv_bfloat16 h0,lo0,h1,lo1;
        split2(oA[ni][0] * inv0, h0, lo0);
        split2(oA[ni][1] * inv0, h1, lo1);
        size_t i0 = (size_t)row0 * D_MODEL + col;
        *(__nv_bfloat162*)&Oh[i0] = __nv_bfloat162(h0, h1);
        *(__nv_bfloat162*)&Ol[i0] = __nv_bfloat162(lo0, lo1);
        split2(oA[ni][2] * inv1, h0, lo0);
        split2(oA[ni][3] * inv1, h1, lo1);
        size_t i1 = (size_t)(row0 + 8) * D_MODEL + col;
        *(__nv_bfloat162*)&Oh[i1] = __nv_bfloat162(h0, h1);
        *(__nv_bfloat162*)&Ol[i1] = __nv_bfloat162(lo0, lo1);
    }
}

// ======================= fused split-K reduce + layernorm ====================
__global__ void layernorm_sum_kernel(const float* __restrict__ P0, const float* __restrict__ P1,
                                     const float* __restrict__ bias, const float* __restrict__ Res,
                                     const float* __restrict__ g, const float* __restrict__ be,
                                     float* __restrict__ out,
                                     __nv_bfloat16* __restrict__ oh, __nv_bfloat16* __restrict__ ol,
                                     int transpose_out)
{
    __shared__ float rs[8], rq[8];
    const int row = blockIdx.x;
    const int tid = threadIdx.x;

    float4 a = ((const float4*)(P0 + (size_t)row * D_MODEL))[tid];
    float4 b = ((const float4*)(P1 + (size_t)row * D_MODEL))[tid];
    float4 r = ((const float4*)(Res + (size_t)row * D_MODEL))[tid];
    float4 bb = ((const float4*)bias)[tid];
    float4 v;
    v.x = a.x + b.x + bb.x + r.x;
    v.y = a.y + b.y + bb.y + r.y;
    v.z = a.z + b.z + bb.z + r.z;
    v.w = a.w + b.w + bb.w + r.w;

    float s = v.x + v.y + v.z + v.w;
    float q = v.x*v.x + v.y*v.y + v.z*v.z + v.w*v.w;
#pragma unroll
    for (int o = 16; o >= 1; o >>= 1) {
        s += __shfl_xor_sync(0xffffffffu, s, o);
        q += __shfl_xor_sync(0xffffffffu, q, o);
    }
    if ((tid & 31) == 0) { rs[tid >> 5] = s; rq[tid >> 5] = q; }
    __syncthreads();
    s = 0.f; q = 0.f;
#pragma unroll
    for (int i = 0; i < 8; i++) { s += rs[i]; q += rq[i]; }

    float mean = s * (1.f / D_MODEL);
    float var  = q * (1.f / D_MODEL) - mean * mean;
    float rstd = rsqrtf(var + EPS);

    float4 g4 = ((const float4*)g)[tid];
    float4 b4 = ((const float4*)be)[tid];
    float4 o4;
    o4.x = (v.x - mean) * rstd * g4.x + b4.x;
    o4.y = (v.y - mean) * rstd * g4.y + b4.y;
    o4.z = (v.z - mean) * rstd * g4.z + b4.z;
    o4.w = (v.w - mean) * rstd * g4.w + b4.w;

    size_t orow = row;
    if (transpose_out) {
        int b_ = row >> 11;
        int s_ = row & 2047;
        orow = (size_t)s_ * BATCH + b_;
    }
    ((float4*)(out + orow * D_MODEL))[tid] = o4;

    if (oh) {
        __nv_bfloat16 h0,l0,h1,l1,h2,l2,h3,l3;
        split2(o4.x,h0,l0); split2(o4.y,h1,l1); split2(o4.z,h2,l2); split2(o4.w,h3,l3);
        size_t o = (size_t)row * D_MODEL + tid * 4;
        *(__nv_bfloat162*)(oh + o)     = __nv_bfloat162(h0, h1);
        *(__nv_bfloat162*)(oh + o + 2) = __nv_bfloat162(h2, h3);
        *(__nv_bfloat162*)(ol + o)     = __nv_bfloat162(l0, l1);
        *(__nv_bfloat162*)(ol + o + 2) = __nv_bfloat162(l2, l3);
    }
}

// ======================= launch =============================================
extern "C" void kernel_launch(void* const* d_in, const int* in_sizes, int n_in,
                              void* d_out, int out_size)
{
    const float* x   = (const float*)d_in[0];
    const float* Wq  = (const float*)d_in[1];
    const float* bq  = (const float*)d_in[2];
    const float* Wk  = (const float*)d_in[3];
    const float* bk  = (const float*)d_in[4];
    const float* Wv  = (const float*)d_in[5];
    const float* bv  = (const float*)d_in[6];
    const float* Wo  = (const float*)d_in[7];
    const float* bo  = (const float*)d_in[8];
    const float* W1  = (const float*)d_in[9];
    const float* b1  = (const float*)d_in[10];
    const float* W2  = (const float*)d_in[11];
    const float* b2  = (const float*)d_in[12];
    const float* g1  = (const float*)d_in[13];
    const float* be1 = (const float*)d_in[14];
    const float* g2  = (const float*)d_in[15];
    const float* be2 = (const float*)d_in[16];
    float* out = (float*)d_out;

    float *XB, *P0, *P1, *X1, *bqkv;
    __nv_bfloat16 *XBh, *XBl, *QKVh, *QKVl, *CTXh, *CTXl, *X1h, *X1l, *Hh, *Hl;
    __nv_bfloat16 *Wqkvth, *Wqkvtl, *Woth, *Wotl, *W1th, *W1tl, *W2th, *W2tl;
    cudaGetSymbolAddress((void**)&XB,   g_XB);
    cudaGetSymbolAddress((void**)&XBh,  g_XBh);
    cudaGetSymbolAddress((void**)&XBl,  g_XBl);
    cudaGetSymbolAddress((void**)&QKVh, g_QKVh);
    cudaGetSymbolAddress((void**)&QKVl, g_QKVl);
    cudaGetSymbolAddress((void**)&CTXh, g_CTXh);
    cudaGetSymbolAddress((void**)&CTXl, g_CTXl);
    cudaGetSymbolAddress((void**)&P0,   g_P0);
    cudaGetSymbolAddress((void**)&P1,   g_P1);
    cudaGetSymbolAddress((void**)&X1,   g_X1);
    cudaGetSymbolAddress((void**)&X1h,  g_X1h);
    cudaGetSymbolAddress((void**)&X1l,  g_X1l);
    cudaGetSymbolAddress((void**)&Hh,   g_Hh);
    cudaGetSymbolAddress((void**)&Hl,   g_Hl);
    cudaGetSymbolAddress((void**)&Wqkvth, g_Wqkvth);
    cudaGetSymbolAddress((void**)&Wqkvtl, g_Wqkvtl);
    cudaGetSymbolAddress((void**)&Woth, g_Woth);
    cudaGetSymbolAddress((void**)&Wotl, g_Wotl);
    cudaGetSymbolAddress((void**)&W1th, g_W1th);
    cudaGetSymbolAddress((void**)&W1tl, g_W1tl);
    cudaGetSymbolAddress((void**)&W2th, g_W2th);
    cudaGetSymbolAddress((void**)&W2tl, g_W2tl);
    cudaGetSymbolAddress((void**)&bqkv, g_bqkv);

    cudaFuncSetAttribute(gemm_hmma_kernel, cudaFuncAttributeMaxDynamicSharedMemorySize, GEMM_SMEM);
    cudaFuncSetAttribute(attention_hmma_kernel, cudaFuncAttributeMaxDynamicSharedMemorySize, ATT_SMEM);

    // fused prep
    prep_all_kernel<<<16396, 256>>>(
        x, Wq, Wk, Wv, Wo, W1, W2, bq, bk, bv,
        XB, XBh, XBl,
        Wqkvth, Wqkvtl, Woth, Wotl, W1th, W1tl, W2th, W2tl, bqkv);

    // fused QKV -> bf16 hi/lo (epi 3)
    gemm_hmma_kernel<<<dim3(QKV_N/128, NTOK/128, 1), 256, GEMM_SMEM>>>(
        XBh, XBl, Wqkvth, Wqkvtl, bqkv, nullptr, nullptr, QKVh, QKVl,
        D_MODEL, D_MODEL, QKV_N, 3);

    // HMMA flash attention -> CTX hi/lo (2 CTA/SM)
    attention_hmma_kernel<<<dim3(SEQ/128, BATCH*NHEAD), 256, ATT_SMEM>>>(QKVh, QKVl, CTXh, CTXl);

    // O-proj split-K=2 ; fused reduce+bias+res+LN1 -> X1 (+hi/lo)
    gemm_hmma_kernel<<<dim3(D_MODEL/128, NTOK/128, 2), 256, GEMM_SMEM>>>(
        CTXh, CTXl, Woth, Wotl, nullptr, P0, P1, nullptr, nullptr,
        D_MODEL/2, D_MODEL, D_MODEL, 4);
    layernorm_sum_kernel<<<NTOK, 256>>>(P0, P1, bo, XB, g1, be1, X1, X1h, X1l, 0);

    // FFN1 (+GELU) -> H hi/lo (epi 1)
    gemm_hmma_kernel<<<dim3(D_FF/128, NTOK/128, 1), 256, GEMM_SMEM>>>(
        X1h, X1l, W1th, W1tl, b1, nullptr, nullptr, Hh, Hl,
        D_MODEL, D_MODEL, D_FF, 1);

    // FFN2 split-K=2 ; fused reduce+bias+res+LN2 -> out (transposed)
    gemm_hmma_kernel<<<dim3(D_MODEL/128, NTOK/128, 2), 256, GEMM_SMEM>>>(
        Hh, Hl, W2th, W2tl, nullptr, P0, P1, nullptr, nullptr,
        D_FF/2, D_FF, D_MODEL, 4);
    layernorm_sum_kernel<<<NTOK, 256>>>(P0, P1, b2, X1, g2, be2, out, nullptr, nullptr, 1);
}

// round 15
// speedup vs baseline: 1.1411x; 1.0466x over previous
#include <cuda_runtime.h>
#include <cuda_bf16.h>
#include <cuda.h>
#include <math.h>
#include <stdint.h>

#define D_MODEL 1024
#define NHEAD   16
#define DH      64
#define D_FF    4096
#define SEQ     2048
#define BATCH   2
#define NTOK    (SEQ * BATCH)
#define EPS     1e-5f
#define QKV_N   (3 * D_MODEL)   // 3072

// ======================= helpers ============================================
__device__ __forceinline__ uint32_t smem_to_u32(const void* p) {
    uint32_t a;
    asm("{ .reg .u64 t; cvta.to.shared.u64 t, %1; cvt.u32.u64 %0, t; }" : "=r"(a) : "l"(p));
    return a;
}
__device__ __forceinline__ void cp_async16(uint32_t dst, const void* src) {
    asm volatile("cp.async.cg.shared.global [%0], [%1], 16;" :: "r"(dst), "l"(src) : "memory");
}
#define CP_COMMIT() asm volatile("cp.async.commit_group;" ::: "memory")
#define CP_WAIT(n)  asm volatile("cp.async.wait_group %0;" :: "n"(n) : "memory")

__device__ __forceinline__ void ldm_x4(uint32_t* r, uint32_t addr) {
    asm volatile("ldmatrix.sync.aligned.m8n8.x4.shared.b16 {%0,%1,%2,%3}, [%4];"
        : "=r"(r[0]), "=r"(r[1]), "=r"(r[2]), "=r"(r[3]) : "r"(addr));
}
__device__ __forceinline__ void ldm_x4_t(uint32_t* r, uint32_t addr) {
    asm volatile("ldmatrix.sync.aligned.m8n8.x4.trans.shared.b16 {%0,%1,%2,%3}, [%4];"
        : "=r"(r[0]), "=r"(r[1]), "=r"(r[2]), "=r"(r[3]) : "r"(addr));
}
__device__ __forceinline__ void mma_bf16(float* d, const uint32_t* a, const uint32_t* b) {
    asm volatile("mma.sync.aligned.m16n8k16.row.col.f32.bf16.bf16.f32 "
        "{%0,%1,%2,%3}, {%4,%5,%6,%7}, {%8,%9}, {%0,%1,%2,%3};"
        : "+f"(d[0]), "+f"(d[1]), "+f"(d[2]), "+f"(d[3])
        : "r"(a[0]), "r"(a[1]), "r"(a[2]), "r"(a[3]), "r"(b[0]), "r"(b[1]));
}
__device__ __forceinline__ void split2(float x, __nv_bfloat16& h, __nv_bfloat16& l) {
    h = __float2bfloat16_rn(x);
    l = __float2bfloat16_rn(x - __bfloat162float(h));
}
__device__ __forceinline__ uint32_t pk(__nv_bfloat16 a, __nv_bfloat16 b) {
    __nv_bfloat162 t(a, b);
    return *reinterpret_cast<uint32_t*>(&t);
}
// 64B-pitch smem swizzle: 16B segment rotated by (row>>1)&3 -> LDSM conflict-free
__device__ __forceinline__ uint32_t swz(uint32_t row, uint32_t seg) {
    return row * 64u + ((seg ^ ((row >> 1) & 3u)) << 4);
}

// ======================= scratch ============================================
__device__ float          g_XB  [NTOK * D_MODEL];
__device__ __nv_bfloat16  g_XBh [NTOK * D_MODEL];
__device__ __nv_bfloat16  g_XBl [NTOK * D_MODEL];
__device__ __nv_bfloat16  g_QKVh[NTOK * QKV_N];
__device__ __nv_bfloat16  g_QKVl[NTOK * QKV_N];
__device__ __nv_bfloat16  g_CTXh[NTOK * D_MODEL];
__device__ __nv_bfloat16  g_CTXl[NTOK * D_MODEL];
__device__ float          g_P0  [NTOK * D_MODEL];
__device__ float          g_P1  [NTOK * D_MODEL];
__device__ float          g_X1  [NTOK * D_MODEL];
__device__ __nv_bfloat16  g_X1h [NTOK * D_MODEL];
__device__ __nv_bfloat16  g_X1l [NTOK * D_MODEL];
__device__ __nv_bfloat16  g_Hh  [NTOK * D_FF];
__device__ __nv_bfloat16  g_Hl  [NTOK * D_FF];
__device__ __nv_bfloat16  g_Wqkvth[QKV_N * D_MODEL];
__device__ __nv_bfloat16  g_Wqkvtl[QKV_N * D_MODEL];
__device__ __nv_bfloat16  g_Woth[D_MODEL * D_MODEL];
__device__ __nv_bfloat16  g_Wotl[D_MODEL * D_MODEL];
__device__ __nv_bfloat16  g_W1th[D_FF * D_MODEL];
__device__ __nv_bfloat16  g_W1tl[D_FF * D_MODEL];
__device__ __nv_bfloat16  g_W2th[D_MODEL * D_FF];
__device__ __nv_bfloat16  g_W2tl[D_MODEL * D_FF];
__device__ float          g_bqkv[QKV_N];

// ======================= fused prep kernel ===================================
__global__ void prep_all_kernel(
    const float* __restrict__ x,
    const float* __restrict__ Wq, const float* __restrict__ Wk,
    const float* __restrict__ Wv, const float* __restrict__ Wo,
    const float* __restrict__ W1, const float* __restrict__ W2,
    const float* __restrict__ bq, const float* __restrict__ bk, const float* __restrict__ bv,
    float* __restrict__ xb, __nv_bfloat16* __restrict__ xh, __nv_bfloat16* __restrict__ xl,
    __nv_bfloat16* __restrict__ Wqkvth, __nv_bfloat16* __restrict__ Wqkvtl,
    __nv_bfloat16* __restrict__ Woth,   __nv_bfloat16* __restrict__ Wotl,
    __nv_bfloat16* __restrict__ W1th,   __nv_bfloat16* __restrict__ W1tl,
    __nv_bfloat16* __restrict__ W2th,   __nv_bfloat16* __restrict__ W2tl,
    float* __restrict__ bqkv)
{
    __shared__ float t[32][33];
    const int blk = blockIdx.x;
    const int tid = threadIdx.x;

    if (blk >= 16384) {
        int i = (blk - 16384) * 256 + tid;
        if (i < QKV_N) {
            const float* s = (i < 1024) ? bq : (i < 2048) ? bk : bv;
            bqkv[i] = s[i & 1023];
        }
        return;
    }
    if (blk >= 12288) {
        int idx = (blk - 12288) * 256 + tid;
        int r  = idx >> 8;
        int c4 = idx & 255;
        int b_ = r / SEQ;
        int s_ = r - b_ * SEQ;
        float4 v = ((const float4*)x)[(size_t)(s_ * BATCH + b_) * 256 + c4];
        ((float4*)xb)[idx] = v;
        __nv_bfloat16 h0,l0,h1,l1,h2,l2,h3,l3;
        split2(v.x,h0,l0); split2(v.y,h1,l1); split2(v.z,h2,l2); split2(v.w,h3,l3);
        __nv_bfloat162* ph = (__nv_bfloat162*)(xh + (size_t)idx * 4);
        __nv_bfloat162* pl = (__nv_bfloat162*)(xl + (size_t)idx * 4);
        ph[0] = __nv_bfloat162(h0, h1); ph[1] = __nv_bfloat162(h2, h3);
        pl[0] = __nv_bfloat162(l0, l1); pl[1] = __nv_bfloat162(l2, l3);
        return;
    }

    const float* W; __nv_bfloat16 *Oh, *Ol;
    int K, N, bx, by;
    if (blk < 4096) {
        int m = blk >> 10;
        int j = blk & 1023;
        K = D_MODEL; N = D_MODEL;
        bx = j & 31; by = j >> 5;
        if (m == 0)      { W = Wq; Oh = Wqkvth;                                Ol = Wqkvtl; }
        else if (m == 1) { W = Wk; Oh = Wqkvth + (size_t)D_MODEL*D_MODEL;      Ol = Wqkvtl + (size_t)D_MODEL*D_MODEL; }
        else if (m == 2) { W = Wv; Oh = Wqkvth + (size_t)2*D_MODEL*D_MODEL;    Ol = Wqkvtl + (size_t)2*D_MODEL*D_MODEL; }
        else             { W = Wo; Oh = Woth;                                  Ol = Wotl; }
    } else if (blk < 8192) {
        int j = blk - 4096;
        K = D_MODEL; N = D_FF;
        bx = j & 127; by = j >> 7;
        W = W1; Oh = W1th; Ol = W1tl;
    } else {
        int j = blk - 8192;
        K = D_FF; N = D_MODEL;
        bx = j & 31; by = j >> 5;
        W = W2; Oh = W2th; Ol = W2tl;
    }
    int n0 = bx * 32, k0 = by * 32;
    int tx = tid & 31, ty = tid >> 5;
#pragma unroll
    for (int i = 0; i < 4; i++)
        t[ty + 8*i][tx] = W[(size_t)(k0 + ty + 8*i) * N + n0 + tx];
    __syncthreads();
#pragma unroll
    for (int i = 0; i < 4; i++) {
        float v = t[tx][ty + 8*i];
        __nv_bfloat16 h, l; split2(v, h, l);
        size_t o = (size_t)(n0 + ty + 8*i) * K + k0 + tx;
        Oh[o] = h; Ol[o] = l;
    }
}

// ======================= HMMA bf16x3 GEMM (swizzled, 3-stage, 2 CTA/SM) =====
// epi 1: +bias,GELU -> Ch,Cl ; 3: +bias -> Ch,Cl ; 4: raw fp32 -> (Cf0|Cf1)
#define GK        32
#define PARTB     (128 * 64)        // 8192 (64B pitch, swizzled)
#define STAGEB    (4 * PARTB)       // 32768
#define GEMM_SMEM (3 * STAGEB)      // 98304

__global__ __launch_bounds__(256, 2)
void gemm_hmma_kernel(const __nv_bfloat16* __restrict__ Ah, const __nv_bfloat16* __restrict__ Al,
                      const __nv_bfloat16* __restrict__ Bth, const __nv_bfloat16* __restrict__ Btl,
                      const float* __restrict__ bias,
                      float* __restrict__ Cf0, float* __restrict__ Cf1,
                      __nv_bfloat16* __restrict__ Ch, __nv_bfloat16* __restrict__ Cl,
                      int Klen, int LDK, int N, int epi)
{
    extern __shared__ char smem[];
    const uint32_t sbase = smem_to_u32(smem);

    const int tid = threadIdx.x;
    const int wid = tid >> 5;
    const int lid = tid & 31;
    const int wm = wid >> 2;
    const int wn = wid & 3;
    const int brow = blockIdx.y * 128;
    const int bcol = blockIdx.x * 128;
    const int kz = blockIdx.z;
    const int NC = Klen / GK;

    const size_t kofs = (size_t)kz * Klen;
    Ah += kofs; Al += kofs; Bth += kofs; Btl += kofs;
    float* Cf = kz ? Cf1 : Cf0;

    float acc[4][4][4];
#pragma unroll
    for (int mi = 0; mi < 4; mi++)
#pragma unroll
        for (int ni = 0; ni < 4; ni++)
#pragma unroll
            for (int e = 0; e < 4; e++) acc[mi][ni][e] = 0.f;

    auto load_chunk = [&](int kc, int s) {
        const int kb = kc * GK;
        const __nv_bfloat16* srcs[4] = { Ah, Al, Bth, Btl };
#pragma unroll
        for (int p = 0; p < 8; p++) {
            int i = tid + p * 256;
            int part = i >> 9;
            int j = i & 511;
            int r = j >> 2, c = j & 3;
            int grow = ((part < 2) ? brow : bcol) + r;
            const __nv_bfloat16* src = srcs[part] + (size_t)grow * LDK + kb + c * 8;
            cp_async16(sbase + s * STAGEB + part * PARTB + swz(r, c), src);
        }
        CP_COMMIT();
    };

    const int a_row = lid & 15;
    const int a_kof = (lid >> 4) * 8;
    const int bkey  = (lid & 7) + 8 * (lid >> 4);
    const int bkof  = ((lid >> 3) & 1) * 8;

    load_chunk(0, 0);
    load_chunk(1, 1);

    for (int kc = 0; kc < NC; kc++) {
        if (kc + 1 < NC) { CP_WAIT(1); } else { CP_WAIT(0); }
        __syncthreads();                    // buf[kc] visible; buf[kc+2]'s target free

        const uint32_t st = sbase + (kc % 3) * STAGEB;
        const uint32_t ah_b = st;
        const uint32_t al_b = st + PARTB;
        const uint32_t bh_b = st + 2 * PARTB;
        const uint32_t bl_b = st + 3 * PARTB;

        // ---- ks = 0: LDSM first, then prefetch chunk kc+2 ----
        uint32_t ahf[4][4], alf[4][4], bhf[2][4], blf[2][4];
#pragma unroll
        for (int mi = 0; mi < 4; mi++) {
            uint32_t row = wm * 64 + mi * 16 + a_row;
            uint32_t off = swz(row, a_kof >> 3);
            ldm_x4(ahf[mi], ah_b + off);
            ldm_x4(alf[mi], al_b + off);
        }
#pragma unroll
        for (int nip = 0; nip < 2; nip++) {
            uint32_t row = wn * 32 + nip * 16 + bkey;
            uint32_t off = swz(row, bkof >> 3);
            ldm_x4(bhf[nip], bh_b + off);
            ldm_x4(blf[nip], bl_b + off);
        }
        if (kc + 2 < NC) load_chunk(kc + 2, (kc + 2) % 3);

#pragma unroll
        for (int mi = 0; mi < 4; mi++)
#pragma unroll
            for (int nip = 0; nip < 2; nip++) {
                mma_bf16(acc[mi][2*nip],   ahf[mi], bhf[nip]);
                mma_bf16(acc[mi][2*nip+1], ahf[mi], bhf[nip] + 2);
                mma_bf16(acc[mi][2*nip],   ahf[mi], blf[nip]);
                mma_bf16(acc[mi][2*nip+1], ahf[mi], blf[nip] + 2);
                mma_bf16(acc[mi][2*nip],   alf[mi], bhf[nip]);
                mma_bf16(acc[mi][2*nip+1], alf[mi], bhf[nip] + 2);
            }

        // ---- ks = 1 ----
#pragma unroll
        for (int mi = 0; mi < 4; mi++) {
            uint32_t row = wm * 64 + mi * 16 + a_row;
            uint32_t off = swz(row, (16 + a_kof) >> 3);
            ldm_x4(ahf[mi], ah_b + off);
            ldm_x4(alf[mi], al_b + off);
        }
#pragma unroll
        for (int nip = 0; nip < 2; nip++) {
            uint32_t row = wn * 32 + nip * 16 + bkey;
            uint32_t off = swz(row, (16 + bkof) >> 3);
            ldm_x4(bhf[nip], bh_b + off);
            ldm_x4(blf[nip], bl_b + off);
        }
#pragma unroll
        for (int mi = 0; mi < 4; mi++)
#pragma unroll
            for (int nip = 0; nip < 2; nip++) {
                mma_bf16(acc[mi][2*nip],   ahf[mi], bhf[nip]);
                mma_bf16(acc[mi][2*nip+1], ahf[mi], bhf[nip] + 2);
                mma_bf16(acc[mi][2*nip],   ahf[mi], blf[nip]);
                mma_bf16(acc[mi][2*nip+1], ahf[mi], blf[nip] + 2);
                mma_bf16(acc[mi][2*nip],   alf[mi], bhf[nip]);
                mma_bf16(acc[mi][2*nip+1], alf[mi], bhf[nip] + 2);
            }
    }

    const int r_in = lid >> 2;
    const int c_in = (lid & 3) * 2;
#pragma unroll
    for (int mi = 0; mi < 4; mi++) {
#pragma unroll
        for (int ni = 0; ni < 4; ni++) {
            int row0 = brow + wm * 64 + mi * 16 + r_in;
            int col  = bcol + wn * 32 + ni * 8 + c_in;
            size_t i0 = (size_t)row0 * N + col;
            size_t i1 = (size_t)(row0 + 8) * N + col;
            if (epi == 4) {
                *(float2*)&Cf[i0] = make_float2(acc[mi][ni][0], acc[mi][ni][1]);
                *(float2*)&Cf[i1] = make_float2(acc[mi][ni][2], acc[mi][ni][3]);
            } else {
                float2 bv = *(const float2*)&bias[col];
                float v[4];
                v[0] = acc[mi][ni][0] + bv.x;
                v[1] = acc[mi][ni][1] + bv.y;
                v[2] = acc[mi][ni][2] + bv.x;
                v[3] = acc[mi][ni][3] + bv.y;
                if (epi == 1) {
#pragma unroll
                    for (int e = 0; e < 4; e++)
                        v[e] = 0.5f * v[e] * (1.f + erff(v[e] * 0.70710678118654752f));
                }
                __nv_bfloat16 h0,l0,h1,l1;
                split2(v[0], h0, l0); split2(v[1], h1, l1);
                *(__nv_bfloat162*)&Ch[i0] = __nv_bfloat162(h0, h1);
                *(__nv_bfloat162*)&Cl[i0] = __nv_bfloat162(l0, l1);
                split2(v[2], h0, l0); split2(v[3], h1, l1);
                *(__nv_bfloat162*)&Ch[i1] = __nv_bfloat162(h0, h1);
                *(__nv_bfloat162*)&Cl[i1] = __nv_bfloat162(l0, l1);
            }
        }
    }
}

// ======================= HMMA flash attention (2 CTA/SM) =====================
#define AP_B    144
#define Q_PART  (128 * AP_B)
#define KV_PART (64 * AP_B)
#define ATT_SMEM (2 * Q_PART + 8 * KV_PART) // 110592

__global__ __launch_bounds__(256, 2)
void attention_hmma_kernel(const __nv_bfloat16* __restrict__ QKVh,
                           const __nv_bfloat16* __restrict__ QKVl,
                           __nv_bfloat16* __restrict__ Oh, __nv_bfloat16* __restrict__ Ol)
{
    extern __shared__ char smem[];
    const uint32_t sbase = smem_to_u32(smem);
    const int tid = threadIdx.x, wid = tid >> 5, lid = tid & 31;
    const int qt = blockIdx.x, bh = blockIdx.y;
    const int b_ = bh >> 4, h_ = bh & 15;
    const int qrow0 = b_ * SEQ + qt * 128;
    const int krow0 = b_ * SEQ;
    const size_t LDQ = QKV_N;
    const uint32_t ringb = sbase + 2 * Q_PART;

    {
        const __nv_bfloat16* srcs[2] = { QKVh, QKVl };
#pragma unroll
        for (int t = 0; t < 8; t++) {
            int i = tid + t * 256;
            int part = i >> 10, j = i & 1023, r = j >> 3, c = j & 7;
            cp_async16(sbase + part * Q_PART + r * AP_B + c * 16,
                       srcs[part] + (size_t)(qrow0 + r) * LDQ + h_ * 64 + c * 8);
        }
        CP_COMMIT();
    }
    auto load_kv = [&](int kt, int s) {
        const __nv_bfloat16* srcs[4] = { QKVh, QKVl, QKVh, QKVl };
        const int coff[4] = { 1024, 1024, 2048, 2048 };
#pragma unroll
        for (int t = 0; t < 8; t++) {
            int i = tid + t * 256;
            int part = i >> 9, j = i & 511, r = j >> 3, c = j & 7;
            cp_async16(ringb + s * (4 * KV_PART) + part * KV_PART + r * AP_B + c * 16,
                       srcs[part] + (size_t)(krow0 + kt * 64 + r) * LDQ + coff[part] + h_ * 64 + c * 8);
        }
        CP_COMMIT();
    };
    load_kv(0, 0);

    float m0 = -INFINITY, m1 = -INFINITY, l0 = 0.f, l1 = 0.f;
    float oA[8][4];
#pragma unroll
    for (int ni = 0; ni < 8; ni++)
#pragma unroll
        for (int e = 0; e < 4; e++) oA[ni][e] = 0.f;

    const int arow = lid & 15;
    const int akof = (lid >> 4) * 8;
    const int bkey = (lid & 7) + 8 * (lid >> 4);
    const int bkof = ((lid >> 3) & 1) * 8;
    const int vkey = (lid & 7) + 8 * ((lid >> 3) & 1);
    const int vdh  = (lid >> 4) * 8;

    for (int kt = 0; kt < 32; kt++) {
        CP_WAIT(0);
        __syncthreads();
        if (kt < 31) load_kv(kt + 1, (kt + 1) & 1);
        const uint32_t kb = ringb + (kt & 1) * (4 * KV_PART);

        float sc[8][4];
#pragma unroll
        for (int ni = 0; ni < 8; ni++)
#pragma unroll
            for (int e = 0; e < 4; e++) sc[ni][e] = 0.f;

#pragma unroll
        for (int ks = 0; ks < 4; ks++) {
            uint32_t aQh[4], aQl[4];
            {
                uint32_t qoff = (wid * 16 + arow) * AP_B + (ks * 16 + akof) * 2;
                ldm_x4(aQh, sbase + qoff);
                ldm_x4(aQl, sbase + Q_PART + qoff);
            }
            uint32_t bh4[4][4], bl4[4][4];
#pragma unroll
            for (int nip = 0; nip < 4; nip++) {
                uint32_t off = (nip * 16 + bkey) * AP_B + (ks * 16 + bkof) * 2;
                ldm_x4(bh4[nip], kb + off);
                ldm_x4(bl4[nip], kb + KV_PART + off);
            }
#pragma unroll
            for (int nip = 0; nip < 4; nip++) {
                mma_bf16(sc[2*nip],   aQh, bh4[nip]);
                mma_bf16(sc[2*nip+1], aQh, bh4[nip] + 2);
            }
#pragma unroll
            for (int nip = 0; nip < 4; nip++) {
                mma_bf16(sc[2*nip],   aQh, bl4[nip]);
                mma_bf16(sc[2*nip+1], aQh, bl4[nip] + 2);
            }
#pragma unroll
            for (int nip = 0; nip < 4; nip++) {
                mma_bf16(sc[2*nip],   aQl, bh4[nip]);
                mma_bf16(sc[2*nip+1], aQl, bh4[nip] + 2);
            }
        }

        float mx0 = -INFINITY, mx1 = -INFINITY;
#pragma unroll
        for (int ni = 0; ni < 8; ni++) {
#pragma unroll
            for (int e = 0; e < 4; e++) sc[ni][e] *= 0.125f;
            mx0 = fmaxf(mx0, fmaxf(sc[ni][0], sc[ni][1]));
            mx1 = fmaxf(mx1, fmaxf(sc[ni][2], sc[ni][3]));
        }
        mx0 = fmaxf(mx0, __shfl_xor_sync(0xffffffffu, mx0, 1));
        mx0 = fmaxf(mx0, __shfl_xor_sync(0xffffffffu, mx0, 2));
        mx1 = fmaxf(mx1, __shfl_xor_sync(0xffffffffu, mx1, 1));
        mx1 = fmaxf(mx1, __shfl_xor_sync(0xffffffffu, mx1, 2));
        float mn0 = fmaxf(m0, mx0), mn1 = fmaxf(m1, mx1);
        float f0 = __expf(m0 - mn0), f1 = __expf(m1 - mn1);
        float r0 = 0.f, r1 = 0.f;
#pragma unroll
        for (int ni = 0; ni < 8; ni++) {
            sc[ni][0] = __expf(sc[ni][0] - mn0);
            sc[ni][1] = __expf(sc[ni][1] - mn0);
            sc[ni][2] = __expf(sc[ni][2] - mn1);
            sc[ni][3] = __expf(sc[ni][3] - mn1);
            r0 += sc[ni][0] + sc[ni][1];
            r1 += sc[ni][2] + sc[ni][3];
        }
        r0 += __shfl_xor_sync(0xffffffffu, r0, 1);
        r0 += __shfl_xor_sync(0xffffffffu, r0, 2);
        r1 += __shfl_xor_sync(0xffffffffu, r1, 1);
        r1 += __shfl_xor_sync(0xffffffffu, r1, 2);
        l0 = l0 * f0 + r0;  l1 = l1 * f1 + r1;
        m0 = mn0;           m1 = mn1;
#pragma unroll
        for (int ni = 0; ni < 8; ni++) {
            oA[ni][0] *= f0; oA[ni][1] *= f0;
            oA[ni][2] *= f1; oA[ni][3] *= f1;
        }

#pragma unroll
        for (int ks = 0; ks < 4; ks++) {
            uint32_t ah[4], al[4];
            {
                __nv_bfloat16 h0,l0b,h1,l1b;
                split2(sc[2*ks][0],h0,l0b);   split2(sc[2*ks][1],h1,l1b);   ah[0]=pk(h0,h1); al[0]=pk(l0b,l1b);
                split2(sc[2*ks][2],h0,l0b);   split2(sc[2*ks][3],h1,l1b);   ah[1]=pk(h0,h1); al[1]=pk(l0b,l1b);
                split2(sc[2*ks+1][0],h0,l0b); split2(sc[2*ks+1][1],h1,l1b); ah[2]=pk(h0,h1); al[2]=pk(l0b,l1b);
                split2(sc[2*ks+1][2],h0,l0b); split2(sc[2*ks+1][3],h1,l1b); ah[3]=pk(h0,h1); al[3]=pk(l0b,l1b);
            }
            uint32_t vh4[4][4], vl4[4][4];
#pragma unroll
            for (int nip = 0; nip < 4; nip++) {
                uint32_t off = (ks * 16 + vkey) * AP_B + (nip * 16 + vdh) * 2;
                ldm_x4_t(vh4[nip], kb + 2 * KV_PART + off);
                ldm_x4_t(vl4[nip], kb + 3 * KV_PART + off);
            }
#pragma unroll
            for (int nip = 0; nip < 4; nip++) {
                mma_bf16(oA[2*nip],   ah, vh4[nip]);
                mma_bf16(oA[2*nip+1], ah, vh4[nip] + 2);
            }
#pragma unroll
            for (int nip = 0; nip < 4; nip++) {
                mma_bf16(oA[2*nip],   ah, vl4[nip]);
                mma_bf16(oA[2*nip+1], ah, vl4[nip] + 2);
            }
#pragma unroll
            for (int nip = 0; nip < 4; nip++) {
                mma_bf16(oA[2*nip],   al, vh4[nip]);
                mma_bf16(oA[2*nip+1], al, vh4[nip] + 2);
            }
        }
    }

    const float inv0 = 1.f / l0, inv1 = 1.f / l1;
    const int row0 = qrow0 + wid * 16 + (lid >> 2);
    const int colb = h_ * 64 + (lid & 3) * 2;
#pragma unroll
    for (int ni = 0; ni < 8; ni++) {
        int col = colb + ni * 8;
        __nv_bfloat16 h0,lo0,h1,lo1;
        split2(oA[ni][0] * inv0, h0, lo0);
        split2(oA[ni][1] * inv0, h1, lo1);
        size_t i0 = (size_t)row0 * D_MODEL + col;
        *(__nv_bfloat162*)&Oh[i0] = __nv_bfloat162(h0, h1);
        *(__nv_bfloat162*)&Ol[i0] = __nv_bfloat162(lo0, lo1);
        split2(oA[ni][2] * inv1, h0, lo0);
        split2(oA[ni][3] * inv1, h1, lo1);
        size_t i1 = (size_t)(row0 + 8) * D_MODEL + col;
        *(__nv_bfloat162*)&Oh[i1] = __nv_bfloat162(h0, h1);
        *(__nv_bfloat162*)&Ol[i1] = __nv_bfloat162(lo0, lo1);
    }
}

// ======================= fused split-K reduce + layernorm ====================
__global__ void layernorm_sum_kernel(const float* __restrict__ P0, const float* __restrict__ P1,
                                     const float* __restrict__ bias, const float* __restrict__ Res,
                                     const float* __restrict__ g, const float* __restrict__ be,
                                     float* __restrict__ out,
                                     __nv_bfloat16* __restrict__ oh, __nv_bfloat16* __restrict__ ol,
                                     int transpose_out)
{
    __shared__ float rs[8], rq[8];
    const int row = blockIdx.x;
    const int tid = threadIdx.x;

    float4 a = ((const float4*)(P0 + (size_t)row * D_MODEL))[tid];
    float4 b = ((const float4*)(P1 + (size_t)row * D_MODEL))[tid];
    float4 r = ((const float4*)(Res + (size_t)row * D_MODEL))[tid];
    float4 bb = ((const float4*)bias)[tid];
    float4 v;
    v.x = a.x + b.x + bb.x + r.x;
    v.y = a.y + b.y + bb.y + r.y;
    v.z = a.z + b.z + bb.z + r.z;
    v.w = a.w + b.w + bb.w + r.w;

    float s = v.x + v.y + v.z + v.w;
    float q = v.x*v.x + v.y*v.y + v.z*v.z + v.w*v.w;
#pragma unroll
    for (int o = 16; o >= 1; o >>= 1) {
        s += __shfl_xor_sync(0xffffffffu, s, o);
        q += __shfl_xor_sync(0xffffffffu, q, o);
    }
    if ((tid & 31) == 0) { rs[tid >> 5] = s; rq[tid >> 5] = q; }
    __syncthreads();
    s = 0.f; q = 0.f;
#pragma unroll
    for (int i = 0; i < 8; i++) { s += rs[i]; q += rq[i]; }

    float mean = s * (1.f / D_MODEL);
    float var  = q * (1.f / D_MODEL) - mean * mean;
    float rstd = rsqrtf(var + EPS);

    float4 g4 = ((const float4*)g)[tid];
    float4 b4 = ((const float4*)be)[tid];
    float4 o4;
    o4.x = (v.x - mean) * rstd * g4.x + b4.x;
    o4.y = (v.y - mean) * rstd * g4.y + b4.y;
    o4.z = (v.z - mean) * rstd * g4.z + b4.z;
    o4.w = (v.w - mean) * rstd * g4.w + b4.w;

    size_t orow = row;
    if (transpose_out) {
        int b_ = row >> 11;
        int s_ = row & 2047;
        orow = (size_t)s_ * BATCH + b_;
    }
    ((float4*)(out + orow * D_MODEL))[tid] = o4;

    if (oh) {
        __nv_bfloat16 h0,l0,h1,l1,h2,l2,h3,l3;
        split2(o4.x,h0,l0); split2(o4.y,h1,l1); split2(o4.z,h2,l2); split2(o4.w,h3,l3);
        size_t o = (size_t)row * D_MODEL + tid * 4;
        *(__nv_bfloat162*)(oh + o)     = __nv_bfloat162(h0, h1);
        *(__nv_bfloat162*)(oh + o + 2) = __nv_bfloat162(h2, h3);
        *(__nv_bfloat162*)(ol + o)     = __nv_bfloat162(l0, l1);
        *(__nv_bfloat162*)(ol + o + 2) = __nv_bfloat162(l2, l3);
    }
}

// ======================= launch =============================================
extern "C" void kernel_launch(void* const* d_in, const int* in_sizes, int n_in,
                              void* d_out, int out_size)
{
    const float* x   = (const float*)d_in[0];
    const float* Wq  = (const float*)d_in[1];
    const float* bq  = (const float*)d_in[2];
    const float* Wk  = (const float*)d_in[3];
    const float* bk  = (const float*)d_in[4];
    const float* Wv  = (const float*)d_in[5];
    const float* bv  = (const float*)d_in[6];
    const float* Wo  = (const float*)d_in[7];
    const float* bo  = (const float*)d_in[8];
    const float* W1  = (const float*)d_in[9];
    const float* b1  = (const float*)d_in[10];
    const float* W2  = (const float*)d_in[11];
    const float* b2  = (const float*)d_in[12];
    const float* g1  = (const float*)d_in[13];
    const float* be1 = (const float*)d_in[14];
    const float* g2  = (const float*)d_in[15];
    const float* be2 = (const float*)d_in[16];
    float* out = (float*)d_out;

    float *XB, *P0, *P1, *X1, *bqkv;
    __nv_bfloat16 *XBh, *XBl, *QKVh, *QKVl, *CTXh, *CTXl, *X1h, *X1l, *Hh, *Hl;
    __nv_bfloat16 *Wqkvth, *Wqkvtl, *Woth, *Wotl, *W1th, *W1tl, *W2th, *W2tl;
    cudaGetSymbolAddress((void**)&XB,   g_XB);
    cudaGetSymbolAddress((void**)&XBh,  g_XBh);
    cudaGetSymbolAddress((void**)&XBl,  g_XBl);
    cudaGetSymbolAddress((void**)&QKVh, g_QKVh);
    cudaGetSymbolAddress((void**)&QKVl, g_QKVl);
    cudaGetSymbolAddress((void**)&CTXh, g_CTXh);
    cudaGetSymbolAddress((void**)&CTXl, g_CTXl);
    cudaGetSymbolAddress((void**)&P0,   g_P0);
    cudaGetSymbolAddress((void**)&P1,   g_P1);
    cudaGetSymbolAddress((void**)&X1,   g_X1);
    cudaGetSymbolAddress((void**)&X1h,  g_X1h);
    cudaGetSymbolAddress((void**)&X1l,  g_X1l);
    cudaGetSymbolAddress((void**)&Hh,   g_Hh);
    cudaGetSymbolAddress((void**)&Hl,   g_Hl);
    cudaGetSymbolAddress((void**)&Wqkvth, g_Wqkvth);
    cudaGetSymbolAddress((void**)&Wqkvtl, g_Wqkvtl);
    cudaGetSymbolAddress((void**)&Woth, g_Woth);
    cudaGetSymbolAddress((void**)&Wotl, g_Wotl);
    cudaGetSymbolAddress((void**)&W1th, g_W1th);
    cudaGetSymbolAddress((void**)&W1tl, g_W1tl);
    cudaGetSymbolAddress((void**)&W2th, g_W2th);
    cudaGetSymbolAddress((void**)&W2tl, g_W2tl);
    cudaGetSymbolAddress((void**)&bqkv, g_bqkv);

    cudaFuncSetAttribute(gemm_hmma_kernel, cudaFuncAttributeMaxDynamicSharedMemorySize, GEMM_SMEM);
    cudaFuncSetAttribute(attention_hmma_kernel, cudaFuncAttributeMaxDynamicSharedMemorySize, ATT_SMEM);

    // fused prep
    prep_all_kernel<<<16396, 256>>>(
        x, Wq, Wk, Wv, Wo, W1, W2, bq, bk, bv,
        XB, XBh, XBl,
        Wqkvth, Wqkvtl, Woth, Wotl, W1th, W1tl, W2th, W2tl, bqkv);

    // fused QKV -> bf16 hi/lo (epi 3)
    gemm_hmma_kernel<<<dim3(QKV_N/128, NTOK/128, 1), 256, GEMM_SMEM>>>(
        XBh, XBl, Wqkvth, Wqkvtl, bqkv, nullptr, nullptr, QKVh, QKVl,
        D_MODEL, D_MODEL, QKV_N, 3);

    // HMMA flash attention -> CTX hi/lo (2 CTA/SM)
    attention_hmma_kernel<<<dim3(SEQ/128, BATCH*NHEAD), 256, ATT_SMEM>>>(QKVh, QKVl, CTXh, CTXl);

    // O-proj split-K=2 ; fused reduce+bias+res+LN1 -> X1 (+hi/lo)
    gemm_hmma_kernel<<<dim3(D_MODEL/128, NTOK/128, 2), 256, GEMM_SMEM>>>(
        CTXh, CTXl, Woth, Wotl, nullptr, P0, P1, nullptr, nullptr,
        D_MODEL/2, D_MODEL, D_MODEL, 4);
    layernorm_sum_kernel<<<NTOK, 256>>>(P0, P1, bo, XB, g1, be1, X1, X1h, X1l, 0);

    // FFN1 (+GELU) -> H hi/lo (epi 1)
    gemm_hmma_kernel<<<dim3(D_FF/128, NTOK/128, 1), 256, GEMM_SMEM>>>(
        X1h, X1l, W1th, W1tl, b1, nullptr, nullptr, Hh, Hl,
        D_MODEL, D_MODEL, D_FF, 1);

    // FFN2 split-K=2 ; fused reduce+bias+res+LN2 -> out (transposed)
    gemm_hmma_kernel<<<dim3(D_MODEL/128, NTOK/128, 2), 256, GEMM_SMEM>>>(
        Hh, Hl, W2th, W2tl, nullptr, P0, P1, nullptr, nullptr,
        D_FF/2, D_FF, D_MODEL, 4);
    layernorm_sum_kernel<<<NTOK, 256>>>(P0, P1, b2, X1, g2, be2, out, nullptr, nullptr, 1);
}